// round 1
// baseline (speedup 1.0000x reference)
#include <cuda_runtime.h>
#include <cuda_bf16.h>
#include <math.h>

// ---------------------------------------------------------------------------
// Scratch (device globals; allocation-free)
// ---------------------------------------------------------------------------
#define BATCH 64
#define IMG 224
#define HW  (IMG*IMG)          // 50176

__device__ float g_col[118013952];              // im2col scratch (max: stem 147*802816)
__device__ float g_h0[64LL*64*112*112];         // 51,380,224
__device__ float g_h1[128LL*64*56*56];          // 25,690,112
__device__ float g_h2[256LL*64*28*28];          // 12,845,056
__device__ float g_h3[512LL*64*14*14];          //  6,422,528
__device__ float g_hd1[32LL*64*112*112];        // 25,690,112
__device__ float g_hd2[64LL*64*56*56];          // 12,845,056
__device__ float g_hf1[32LL*64*112*112];
__device__ float g_hf2[64LL*64*56*56];
__device__ float g_dctimg[BATCH*64];
__device__ float g_dctres[BATCH*HW];            // 3,211,264
__device__ float g_wd1s[32*9];
__device__ float g_Wre[HW];
__device__ float g_Wim[HW];
__device__ float g_D8[64];
__device__ float g_Zre[43008LL*224];            // 9,633,792 each
__device__ float g_Zim[43008LL*224];
__device__ float g_Ztre[43008LL*224];
__device__ float g_Ztim[43008LL*224];
__device__ float g_Gre[43008LL*224];
__device__ float g_Gim[43008LL*224];
__device__ float g_fftin[6LL*BATCH*HW];         // 19,267,584
__device__ float g_pooled[BATCH*6272];
__device__ float g_comb[BATCH*1024];
__device__ float g_buf1[BATCH*1024];
__device__ float g_fused[BATCH*512];

// ---------------------------------------------------------------------------
// SGEMM: C[M,N] = alpha*A[M,K]*B[K,N] + beta*C + biasM[m] + biasN[n] (+relu)
// 128x128 tile, BK=8, 256 threads, 8x8 micro-tile per thread.
// ---------------------------------------------------------------------------
__global__ void __launch_bounds__(256) sgemm_k(
    const float* __restrict__ A, const float* __restrict__ B, float* __restrict__ C,
    int M, int N, int K, int ldc, float alpha, float beta,
    const float* __restrict__ biasM, const float* __restrict__ biasN, int relu)
{
    __shared__ float As[8][128];
    __shared__ float Bs[8][128];
    int tid = threadIdx.x;
    int tx = tid & 15, ty = tid >> 4;
    int row0 = blockIdx.y * 128, col0 = blockIdx.x * 128;

    float acc[8][8];
#pragma unroll
    for (int i = 0; i < 8; i++)
#pragma unroll
        for (int j = 0; j < 8; j++) acc[i][j] = 0.f;

    for (int k0 = 0; k0 < K; k0 += 8) {
#pragma unroll
        for (int i = 0; i < 4; i++) {
            int idx = tid + i * 256;
            int m = idx >> 3, kk = idx & 7;
            int gm = row0 + m, gk = k0 + kk;
            float v = 0.f;
            if (gm < M && gk < K) v = A[(long long)gm * K + gk];
            As[kk][m] = v;
        }
#pragma unroll
        for (int i = 0; i < 4; i++) {
            int idx = tid + i * 256;
            int kk = idx >> 7, n = idx & 127;
            int gn = col0 + n, gk = k0 + kk;
            float v = 0.f;
            if (gk < K && gn < N) v = B[(long long)gk * N + gn];
            Bs[kk][n] = v;
        }
        __syncthreads();
#pragma unroll
        for (int kk = 0; kk < 8; kk++) {
            float a[8], b[8];
            *(float4*)&a[0] = *(const float4*)&As[kk][ty * 8];
            *(float4*)&a[4] = *(const float4*)&As[kk][ty * 8 + 4];
            *(float4*)&b[0] = *(const float4*)&Bs[kk][tx * 8];
            *(float4*)&b[4] = *(const float4*)&Bs[kk][tx * 8 + 4];
#pragma unroll
            for (int i = 0; i < 8; i++)
#pragma unroll
                for (int j = 0; j < 8; j++) acc[i][j] += a[i] * b[j];
        }
        __syncthreads();
    }

#pragma unroll
    for (int i = 0; i < 8; i++) {
        int gm = row0 + ty * 8 + i;
        if (gm >= M) continue;
        float bm = biasM ? biasM[gm] : 0.f;
#pragma unroll
        for (int j = 0; j < 8; j++) {
            int gn = col0 + tx * 8 + j;
            if (gn >= N) continue;
            float v = alpha * acc[i][j];
            if (beta != 0.f) v += beta * C[(long long)gm * ldc + gn];
            v += bm;
            if (biasN) v += biasN[gn];
            if (relu) v = fmaxf(v, 0.f);
            C[(long long)gm * ldc + gn] = v;
        }
    }
}

// ---------------------------------------------------------------------------
// im2col: col[(c,kh,kw)][(b,oh,ow)] from src[c*sC + b*sB + ih*W + iw]
// ---------------------------------------------------------------------------
__global__ void im2col_k(const float* __restrict__ src, float* __restrict__ col,
                         int H, int W, int OH, int OW, int KH, int KW,
                         int stride, int pad, long long sC, long long sB,
                         long long Ntot, long long total)
{
    long long gid = (long long)blockIdx.x * blockDim.x + threadIdx.x;
    if (gid >= total) return;
    int k = (int)(gid / Ntot);
    long long n = gid % Ntot;
    int ow = (int)(n % OW);
    long long t = n / OW;
    int oh = (int)(t % OH);
    int b = (int)(t / OH);
    int kw = k % KW;
    int t2 = k / KW;
    int kh = t2 % KH;
    int c = t2 / KH;
    int ih = oh * stride + kh - pad;
    int iw = ow * stride + kw - pad;
    float v = 0.f;
    if (ih >= 0 && ih < H && iw >= 0 && iw < W)
        v = src[c * sC + b * sB + (long long)ih * W + iw];
    col[gid] = v;
}

// ---------------------------------------------------------------------------
// Small kernels
// ---------------------------------------------------------------------------
__global__ void genW_k(float* Wre, float* Wim) {
    int gid = blockIdx.x * blockDim.x + threadIdx.x;
    if (gid >= HW) return;
    int j = gid / IMG, k = gid % IMG;
    int r = (j * k) % IMG;
    float a = 2.f * (float)r / (float)IMG;
    Wre[gid] = cospif(a);
    Wim[gid] = -sinpif(a);
}

__global__ void genD8_k(float* D) {
    int tid = threadIdx.x;
    if (tid >= 64) return;
    int i = tid >> 3, j = tid & 7;
    float v = 0.5f * cospif((float)((2 * j + 1) * i) / 16.f);
    if (i == 0) v *= 0.7071067811865476f;
    D[tid] = v;
}

__global__ void wsum_k(const float* __restrict__ wd1, float* __restrict__ wd1s) {
    int tid = blockIdx.x * blockDim.x + threadIdx.x;
    if (tid >= 288) return;
    int o = tid / 9, r = tid % 9;
    wd1s[tid] = wd1[(o * 3 + 0) * 9 + r] + wd1[(o * 3 + 1) * 9 + r] + wd1[(o * 3 + 2) * 9 + r];
}

// block-mean (gray, 8x8 averaged over 28x28 blocks) then 8x8 DCT: D * M * D^T
__global__ void dct_mean_k(const float* __restrict__ x, const float* __restrict__ D,
                           float* __restrict__ dctimg)
{
    __shared__ float part[8][64];
    __shared__ float Mb[64];
    __shared__ float T[64];
    int b = blockIdx.x;
    int tid = threadIdx.x;            // 512
    int ij = tid & 63, ch = tid >> 6; // 8 chunks
    int i = ij >> 3, j = ij & 7;
    const float* xb = x + (long long)b * 3 * HW;
    float s = 0.f;
    for (int blk = ch; blk < 784; blk += 8) {
        int m = blk / 28, n = blk % 28;
        int idx = (m * 8 + i) * IMG + (n * 8 + j);
        s += 0.299f * xb[idx] + 0.587f * xb[idx + HW] + 0.114f * xb[idx + 2 * HW];
    }
    part[ch][ij] = s;
    __syncthreads();
    if (tid < 64) {
        float t = 0.f;
        for (int c = 0; c < 8; c++) t += part[c][tid];
        Mb[tid] = t * (255.f / 784.f);
    }
    __syncthreads();
    if (tid < 64) {
        float t = 0.f;
        for (int k = 0; k < 8; k++) t += D[i * 8 + k] * Mb[k * 8 + j];
        T[tid] = t;
    }
    __syncthreads();
    if (tid < 64) {
        float o = 0.f;
        for (int k = 0; k < 8; k++) o += T[i * 8 + k] * D[j * 8 + k];
        dctimg[b * 64 + tid] = o;
    }
}

// jax.image.resize bilinear 8x8 -> 224x224 (half-pixel, edge-clamped)
__global__ void resize_k(const float* __restrict__ dctimg, float* __restrict__ out) {
    int gid = blockIdx.x * blockDim.x + threadIdx.x;
    if (gid >= BATCH * HW) return;
    int ow = gid % IMG;
    int t = gid / IMG;
    int oh = t % IMG;
    int b = t / IMG;
    float fh = (oh + 0.5f) * (8.f / 224.f) - 0.5f;
    float fw = (ow + 0.5f) * (8.f / 224.f) - 0.5f;
    fh = fminf(fmaxf(fh, 0.f), 7.f);
    fw = fminf(fmaxf(fw, 0.f), 7.f);
    int h0 = (int)floorf(fh), w0 = (int)floorf(fw);
    int h1 = min(h0 + 1, 7), w1 = min(w0 + 1, 7);
    float ah = fh - (float)h0, aw = fw - (float)w0;
    const float* d = dctimg + b * 64;
    float v00 = d[h0 * 8 + w0], v01 = d[h0 * 8 + w1];
    float v10 = d[h1 * 8 + w0], v11 = d[h1 * 8 + w1];
    out[gid] = (1.f - ah) * ((1.f - aw) * v00 + aw * v01) + ah * ((1.f - aw) * v10 + aw * v11);
}

// batched 224x224 transpose: dst[m][j][i] = src[m][i][j]
__global__ void transpose224_k(const float* __restrict__ src, float* __restrict__ dst) {
    __shared__ float tile[32][33];
    int m = blockIdx.z;
    const float* s = src + (long long)m * HW;
    float* d = dst + (long long)m * HW;
    int i0 = blockIdx.y * 32, j0 = blockIdx.x * 32;
    int tx = threadIdx.x, ty = threadIdx.y;
    tile[ty][tx] = s[(i0 + ty) * IMG + (j0 + tx)];
    __syncthreads();
    d[(j0 + ty) * IMG + (i0 + tx)] = tile[tx][ty];
}

// fft_in[(2c+p)][b][h][w] = G_p[(b*3+c)][w][h]   (transpose + channel reorder)
__global__ void fftin_k(const float* __restrict__ G, float* __restrict__ fftin, int p) {
    __shared__ float tile[32][33];
    int m = blockIdx.z;          // 0..191
    int b = m / 3, c = m % 3;
    const float* s = G + (long long)m * HW;
    float* d = fftin + ((long long)(2 * c + p) * BATCH + b) * HW;
    int i0 = blockIdx.y * 32, j0 = blockIdx.x * 32;
    int tx = threadIdx.x, ty = threadIdx.y;
    tile[ty][tx] = s[(i0 + ty) * IMG + (j0 + tx)];
    __syncthreads();
    d[(j0 + ty) * IMG + (i0 + tx)] = tile[tx][ty];
}

// adaptive avg pool 56x56 -> 7x7; src layout [64][B][56][56]
__global__ void pool7_k(const float* __restrict__ src, float* __restrict__ pooled, int base) {
    int gid = blockIdx.x * blockDim.x + threadIdx.x;
    if (gid >= 64 * BATCH * 49) return;
    int j = gid % 7;
    int t = gid / 7;
    int i = t % 7;
    t /= 7;
    int c = t % 64;
    int b = t / 64;
    const float* s = src + ((long long)c * BATCH + b) * 56 * 56;
    float acc = 0.f;
#pragma unroll
    for (int p = 0; p < 8; p++)
#pragma unroll
        for (int q = 0; q < 8; q++)
            acc += s[(i * 8 + p) * 56 + (j * 8 + q)];
    pooled[b * 6272 + base + c * 49 + i * 7 + j] = acc * (1.f / 64.f);
}

// GAP over 14x14; src layout [512][B][14][14]; write comb[b*1024 + c]
__global__ void gap_k(const float* __restrict__ h3, float* __restrict__ comb) {
    int gid = blockIdx.x * blockDim.x + threadIdx.x;
    if (gid >= 512 * BATCH) return;
    int c = gid / BATCH, b = gid % BATCH;
    const float* s = h3 + ((long long)c * BATCH + b) * 196;
    float acc = 0.f;
    for (int t = 0; t < 196; t++) acc += s[t];
    comb[b * 1024 + c] = acc * (1.f / 196.f);
}

__global__ void cls_k(const float* __restrict__ fused, const float* __restrict__ Wc,
                      const float* __restrict__ bc, const float* __restrict__ temp,
                      float* __restrict__ out)
{
    int tid = threadIdx.x; // 128
    if (tid >= 128) return;
    int b = tid >> 1, j = tid & 1;
    float s = bc[j];
    const float* f = fused + b * 512;
    for (int k = 0; k < 512; k++) s += f[k] * Wc[k * 2 + j];
    out[b * 2 + j] = s;
    out[128 + b * 2 + j] = s / temp[0];
}

// ---------------------------------------------------------------------------
// Host launchers
// ---------------------------------------------------------------------------
static void run_sgemm(const float* A, const float* B, float* C, int M, int N, int K,
                      const float* biasM, const float* biasN, int relu,
                      float alpha = 1.f, float beta = 0.f, int ldc = -1)
{
    if (ldc < 0) ldc = N;
    dim3 grid((N + 127) / 128, (M + 127) / 128);
    sgemm_k<<<grid, 256>>>(A, B, C, M, N, K, ldc, alpha, beta, biasM, biasN, relu);
}

static void run_im2col(const float* src, float* col, int C, int H, int W,
                       int OH, int OW, int KH, int KW, int stride, int pad,
                       long long sC, long long sB)
{
    long long Ntot = (long long)BATCH * OH * OW;
    long long total = (long long)C * KH * KW * Ntot;
    long long blocks = (total + 255) / 256;
    im2col_k<<<(unsigned)blocks, 256>>>(src, col, H, W, OH, OW, KH, KW, stride, pad, sC, sB, Ntot, total);
}

extern "C" void kernel_launch(void* const* d_in, const int* in_sizes, int n_in,
                              void* d_out, int out_size)
{
    const float* x      = (const float*)d_in[0];
    const float* w_stem = (const float*)d_in[1];
    const float* b_stem = (const float*)d_in[2];
    const float* w1     = (const float*)d_in[3];
    const float* b1     = (const float*)d_in[4];
    const float* w2     = (const float*)d_in[5];
    const float* b2     = (const float*)d_in[6];
    const float* w3     = (const float*)d_in[7];
    const float* b3     = (const float*)d_in[8];
    const float* wd1    = (const float*)d_in[9];
    const float* bd1    = (const float*)d_in[10];
    const float* wd2    = (const float*)d_in[11];
    const float* bd2    = (const float*)d_in[12];
    const float* wf1    = (const float*)d_in[13];
    const float* bf1    = (const float*)d_in[14];
    const float* wf2    = (const float*)d_in[15];
    const float* bf2    = (const float*)d_in[16];
    const float* W_freq = (const float*)d_in[17];
    const float* b_freq = (const float*)d_in[18];
    const float* W_fu1  = (const float*)d_in[19];
    const float* b_fu1  = (const float*)d_in[20];
    const float* W_fu2  = (const float*)d_in[21];
    const float* b_fu2  = (const float*)d_in[22];
    const float* W_cls  = (const float*)d_in[23];
    const float* b_cls  = (const float*)d_in[24];
    const float* temp   = (const float*)d_in[25];
    float* out = (float*)d_out;

    float *col, *h0, *h1, *h2, *h3, *hd1, *hd2, *hf1, *hf2;
    float *dctimg, *dctres, *wd1s, *Wre, *Wim, *D8;
    float *Zre, *Zim, *Ztre, *Ztim, *Gre, *Gim, *fftin;
    float *pooled, *comb, *buf1, *fused;
    cudaGetSymbolAddress((void**)&col, g_col);
    cudaGetSymbolAddress((void**)&h0, g_h0);
    cudaGetSymbolAddress((void**)&h1, g_h1);
    cudaGetSymbolAddress((void**)&h2, g_h2);
    cudaGetSymbolAddress((void**)&h3, g_h3);
    cudaGetSymbolAddress((void**)&hd1, g_hd1);
    cudaGetSymbolAddress((void**)&hd2, g_hd2);
    cudaGetSymbolAddress((void**)&hf1, g_hf1);
    cudaGetSymbolAddress((void**)&hf2, g_hf2);
    cudaGetSymbolAddress((void**)&dctimg, g_dctimg);
    cudaGetSymbolAddress((void**)&dctres, g_dctres);
    cudaGetSymbolAddress((void**)&wd1s, g_wd1s);
    cudaGetSymbolAddress((void**)&Wre, g_Wre);
    cudaGetSymbolAddress((void**)&Wim, g_Wim);
    cudaGetSymbolAddress((void**)&D8, g_D8);
    cudaGetSymbolAddress((void**)&Zre, g_Zre);
    cudaGetSymbolAddress((void**)&Zim, g_Zim);
    cudaGetSymbolAddress((void**)&Ztre, g_Ztre);
    cudaGetSymbolAddress((void**)&Ztim, g_Ztim);
    cudaGetSymbolAddress((void**)&Gre, g_Gre);
    cudaGetSymbolAddress((void**)&Gim, g_Gim);
    cudaGetSymbolAddress((void**)&fftin, g_fftin);
    cudaGetSymbolAddress((void**)&pooled, g_pooled);
    cudaGetSymbolAddress((void**)&comb, g_comb);
    cudaGetSymbolAddress((void**)&buf1, g_buf1);
    cudaGetSymbolAddress((void**)&fused, g_fused);

    // ---- init constants ----
    genW_k<<<(HW + 255) / 256, 256>>>(Wre, Wim);
    genD8_k<<<1, 64>>>(D8);
    wsum_k<<<2, 256>>>(wd1, wd1s);

    // ---- CNN backbone ----
    // stem: 3->64, 7x7, s2, pad 2 (SAME), 224->112
    run_im2col(x, col, 3, 224, 224, 112, 112, 7, 7, 2, 2, (long long)HW, 3LL * HW);
    run_sgemm(w_stem, col, h0, 64, 64 * 112 * 112, 147, b_stem, nullptr, 1);
    // conv1: 64->128, 3x3, s2, pad 0 (SAME), 112->56
    run_im2col(h0, col, 64, 112, 112, 56, 56, 3, 3, 2, 0, 64LL * 112 * 112, 112LL * 112);
    run_sgemm(w1, col, h1, 128, 64 * 56 * 56, 576, b1, nullptr, 1);
    // conv2: 128->256, 56->28
    run_im2col(h1, col, 128, 56, 56, 28, 28, 3, 3, 2, 0, 64LL * 56 * 56, 56LL * 56);
    run_sgemm(w2, col, h2, 256, 64 * 28 * 28, 1152, b2, nullptr, 1);
    // conv3: 256->512, 28->14
    run_im2col(h2, col, 256, 28, 28, 14, 14, 3, 3, 2, 0, 64LL * 28 * 28, 28LL * 28);
    run_sgemm(w3, col, h3, 512, 64 * 14 * 14, 2304, b3, nullptr, 1);
    gap_k<<<(512 * BATCH + 255) / 256, 256>>>(h3, comb);

    // ---- DCT branch ----
    dct_mean_k<<<BATCH, 512>>>(x, D8, dctimg);
    resize_k<<<(BATCH * HW + 255) / 256, 256>>>(dctimg, dctres);
    // wd1 (folded to 1 input channel): 1->32, 224->112
    run_im2col(dctres, col, 1, 224, 224, 112, 112, 3, 3, 2, 0, 0LL, (long long)HW);
    run_sgemm(wd1s, col, hd1, 32, 64 * 112 * 112, 9, bd1, nullptr, 1);
    // wd2: 32->64, 112->56
    run_im2col(hd1, col, 32, 112, 112, 56, 56, 3, 3, 2, 0, 64LL * 112 * 112, 112LL * 112);
    run_sgemm(wd2, col, hd2, 64, 64 * 56 * 56, 288, bd2, nullptr, 1);
    pool7_k<<<(64 * BATCH * 49 + 255) / 256, 256>>>(hd2, pooled, 0);

    // ---- FFT branch (DFT as matmul) ----
    // stage 1: row FFT: Z = X * W  (X viewed as [64*3*224, 224])
    run_sgemm(x, Wre, Zre, 43008, 224, 224, nullptr, nullptr, 0);
    run_sgemm(x, Wim, Zim, 43008, 224, 224, nullptr, nullptr, 0);
    {
        dim3 tgrid(7, 7, 192), tblk(32, 32);
        transpose224_k<<<tgrid, tblk>>>(Zre, Ztre);
        transpose224_k<<<tgrid, tblk>>>(Zim, Ztim);
    }
    // stage 2: G = Z^T * W (complex): Gre = Ztre*Wre - Ztim*Wim; Gim = Ztre*Wim + Ztim*Wre
    run_sgemm(Ztre, Wre, Gre, 43008, 224, 224, nullptr, nullptr, 0, 1.f, 0.f);
    run_sgemm(Ztim, Wim, Gre, 43008, 224, 224, nullptr, nullptr, 0, -1.f, 1.f);
    run_sgemm(Ztre, Wim, Gim, 43008, 224, 224, nullptr, nullptr, 0, 1.f, 0.f);
    run_sgemm(Ztim, Wre, Gim, 43008, 224, 224, nullptr, nullptr, 0, 1.f, 1.f);
    {
        dim3 tgrid(7, 7, 192), tblk(32, 32);
        fftin_k<<<tgrid, tblk>>>(Gre, fftin, 0);
        fftin_k<<<tgrid, tblk>>>(Gim, fftin, 1);
    }
    // wf1: 6->32, 224->112
    run_im2col(fftin, col, 6, 224, 224, 112, 112, 3, 3, 2, 0, (long long)BATCH * HW, (long long)HW);
    run_sgemm(wf1, col, hf1, 32, 64 * 112 * 112, 54, bf1, nullptr, 1);
    // wf2: 32->64, 112->56
    run_im2col(hf1, col, 32, 112, 112, 56, 56, 3, 3, 2, 0, 64LL * 112 * 112, 112LL * 112);
    run_sgemm(wf2, col, hf2, 64, 64 * 56 * 56, 288, bf2, nullptr, 1);
    pool7_k<<<(64 * BATCH * 49 + 255) / 256, 256>>>(hf2, pooled, 3136);

    // ---- fusion + classifier ----
    // freq = relu(pooled @ W_freq + b_freq) -> comb[:, 512:1024]
    run_sgemm(pooled, W_freq, comb + 512, 64, 512, 6272, nullptr, b_freq, 1, 1.f, 0.f, 1024);
    run_sgemm(comb, W_fu1, buf1, 64, 1024, 1024, nullptr, b_fu1, 1);
    run_sgemm(buf1, W_fu2, fused, 64, 512, 1024, nullptr, b_fu2, 1);
    cls_k<<<1, 128>>>(fused, W_cls, b_cls, temp, out);
}

// round 2
// speedup vs baseline: 1.1341x; 1.1341x over previous
#include <cuda_runtime.h>
#include <cuda_bf16.h>
#include <math.h>

// ---------------------------------------------------------------------------
#define BATCH 64
#define IMG 224
#define HW  (IMG*IMG)          // 50176

__device__ float g_h0[64LL*64*112*112];         // 51,380,224
__device__ float g_h1[128LL*64*56*56];          // 25,690,112
__device__ float g_h2[256LL*64*28*28];          // 12,845,056
__device__ float g_h3[512LL*64*14*14];          //  6,422,528
__device__ float g_hd1[32LL*64*112*112];        // 25,690,112
__device__ float g_hd2[64LL*64*56*56];          // 12,845,056
__device__ float g_hf1[32LL*64*112*112];
__device__ float g_hf2[64LL*64*56*56];
__device__ float g_dctimg[BATCH*64];
__device__ float g_dctres[BATCH*HW];
__device__ float g_wd1s[32*9];
__device__ float g_Wre[HW];
__device__ float g_Wim[HW];
__device__ float g_D8[64];
__device__ float g_Zre[43008LL*224];
__device__ float g_Zim[43008LL*224];
__device__ float g_Ztre[43008LL*224];
__device__ float g_Ztim[43008LL*224];
__device__ float g_Gre[43008LL*224];
__device__ float g_Gim[43008LL*224];
__device__ float g_fftin[6LL*BATCH*HW];
__device__ float g_pooled[BATCH*6272];
__device__ float g_comb[BATCH*1024];
__device__ float g_buf1[BATCH*1024];
__device__ float g_fused[BATCH*512];

// ---------------------------------------------------------------------------
// Implicit-GEMM conv: dst[co][n] = relu(sum_k W[co][k] * patch(k, n) + bias[co])
// n = (b, oh, ow); k = (c, kh, kw). M-tile = 16*RM, N-tile = 128, BK = 8.
// ---------------------------------------------------------------------------
template<int RM>
__global__ void __launch_bounds__(256) conv_igemm_k(
    const float* __restrict__ src, const float* __restrict__ Wt,
    const float* __restrict__ bias, float* __restrict__ dst,
    int Co, int K, int H, int W, int OH, int OW,
    int KH, int KW, int stride, int pad,
    long long sC, long long sB, int Ntot)
{
    constexpr int TM = 16 * RM;
    __shared__ float As[8][TM];
    __shared__ float Bs[8][128];

    int tid = threadIdx.x;
    int tx = tid & 15, ty = tid >> 4;
    int row0 = blockIdx.y * TM, col0 = blockIdx.x * 128;
    int KHKW = KH * KW;

    // hoisted per-thread N-column decomposition for the B gather
    int n = tid & 127;
    int kq = tid >> 7;               // 0 or 1
    int gn = col0 + n;
    int ow_ = gn % OW;
    int t = gn / OW;
    int oh_ = t % OH;
    int b_ = t / OH;
    int ihb = oh_ * stride - pad;
    int iwb = ow_ * stride - pad;
    const float* sp = src + (long long)b_ * sB;

    float acc[RM][8];
#pragma unroll
    for (int i = 0; i < RM; i++)
#pragma unroll
        for (int j = 0; j < 8; j++) acc[i][j] = 0.f;

    for (int k0 = 0; k0 < K; k0 += 8) {
        // A: weights tile
#pragma unroll
        for (int i = 0; i < TM / 32; i++) {
            int idx = tid + i * 256;
            int m = idx >> 3, kk = idx & 7;
            int gm = row0 + m, gk = k0 + kk;
            As[kk][m] = (gm < Co && gk < K) ? Wt[(long long)gm * K + gk] : 0.f;
        }
        // B: implicit im2col gather
#pragma unroll
        for (int q = 0; q < 4; q++) {
            int kk = kq + q * 2;
            int gk = k0 + kk;
            float v = 0.f;
            if (gk < K) {
                int c = gk / KHKW;
                int r = gk - c * KHKW;
                int kh = r / KW;
                int kw = r - kh * KW;
                int ih = ihb + kh, iw = iwb + kw;
                if ((unsigned)ih < (unsigned)H && (unsigned)iw < (unsigned)W)
                    v = sp[c * sC + (long long)ih * W + iw];
            }
            Bs[kk][n] = v;
        }
        __syncthreads();
#pragma unroll
        for (int kk = 0; kk < 8; kk++) {
            float a[RM], b[8];
            if constexpr (RM == 8) {
                *(float4*)&a[0] = *(const float4*)&As[kk][ty * 8];
                *(float4*)&a[4] = *(const float4*)&As[kk][ty * 8 + 4];
            } else if constexpr (RM == 4) {
                *(float4*)&a[0] = *(const float4*)&As[kk][ty * 4];
            } else {
                a[0] = As[kk][ty * 2];
                a[1] = As[kk][ty * 2 + 1];
            }
            *(float4*)&b[0] = *(const float4*)&Bs[kk][tx * 8];
            *(float4*)&b[4] = *(const float4*)&Bs[kk][tx * 8 + 4];
#pragma unroll
            for (int i = 0; i < RM; i++)
#pragma unroll
                for (int j = 0; j < 8; j++) acc[i][j] += a[i] * b[j];
        }
        __syncthreads();
    }

#pragma unroll
    for (int i = 0; i < RM; i++) {
        int gm = row0 + ty * RM + i;
        if (gm >= Co) continue;
        float bm = bias[gm];
        float* drow = dst + (long long)gm * Ntot;
#pragma unroll
        for (int j = 0; j < 8; j++) {
            int gnj = col0 + tx * 8 + j;
            if (gnj < Ntot) drow[gnj] = fmaxf(acc[i][j] + bm, 0.f);
        }
    }
}

// ---------------------------------------------------------------------------
// Dense SGEMM (DFT + FC): C = alpha*A*B + beta*C + biasN (+relu)
// ---------------------------------------------------------------------------
__global__ void __launch_bounds__(256) sgemm_k(
    const float* __restrict__ A, const float* __restrict__ B, float* __restrict__ C,
    int M, int N, int K, int ldc, float alpha, float beta,
    const float* __restrict__ biasN, int relu)
{
    __shared__ float As[8][128];
    __shared__ float Bs[8][128];
    int tid = threadIdx.x;
    int tx = tid & 15, ty = tid >> 4;
    int row0 = blockIdx.y * 128, col0 = blockIdx.x * 128;

    float acc[8][8];
#pragma unroll
    for (int i = 0; i < 8; i++)
#pragma unroll
        for (int j = 0; j < 8; j++) acc[i][j] = 0.f;

    for (int k0 = 0; k0 < K; k0 += 8) {
#pragma unroll
        for (int i = 0; i < 4; i++) {
            int idx = tid + i * 256;
            int m = idx >> 3, kk = idx & 7;
            int gm = row0 + m, gk = k0 + kk;
            float v = 0.f;
            if (gm < M && gk < K) v = A[(long long)gm * K + gk];
            As[kk][m] = v;
        }
#pragma unroll
        for (int i = 0; i < 4; i++) {
            int idx = tid + i * 256;
            int kk = idx >> 7, nn = idx & 127;
            int gn = col0 + nn, gk = k0 + kk;
            float v = 0.f;
            if (gk < K && gn < N) v = B[(long long)gk * N + gn];
            Bs[kk][nn] = v;
        }
        __syncthreads();
#pragma unroll
        for (int kk = 0; kk < 8; kk++) {
            float a[8], b[8];
            *(float4*)&a[0] = *(const float4*)&As[kk][ty * 8];
            *(float4*)&a[4] = *(const float4*)&As[kk][ty * 8 + 4];
            *(float4*)&b[0] = *(const float4*)&Bs[kk][tx * 8];
            *(float4*)&b[4] = *(const float4*)&Bs[kk][tx * 8 + 4];
#pragma unroll
            for (int i = 0; i < 8; i++)
#pragma unroll
                for (int j = 0; j < 8; j++) acc[i][j] += a[i] * b[j];
        }
        __syncthreads();
    }

#pragma unroll
    for (int i = 0; i < 8; i++) {
        int gm = row0 + ty * 8 + i;
        if (gm >= M) continue;
#pragma unroll
        for (int j = 0; j < 8; j++) {
            int gn = col0 + tx * 8 + j;
            if (gn >= N) continue;
            float v = alpha * acc[i][j];
            if (beta != 0.f) v += beta * C[(long long)gm * ldc + gn];
            if (biasN) v += biasN[gn];
            if (relu) v = fmaxf(v, 0.f);
            C[(long long)gm * ldc + gn] = v;
        }
    }
}

// ---------------------------------------------------------------------------
// Small kernels
// ---------------------------------------------------------------------------
__global__ void genW_k(float* Wre, float* Wim) {
    int gid = blockIdx.x * blockDim.x + threadIdx.x;
    if (gid >= HW) return;
    int j = gid / IMG, k = gid % IMG;
    int r = (j * k) % IMG;
    float a = 2.f * (float)r / (float)IMG;
    Wre[gid] = cospif(a);
    Wim[gid] = -sinpif(a);
}

__global__ void genD8_k(float* D) {
    int tid = threadIdx.x;
    if (tid >= 64) return;
    int i = tid >> 3, j = tid & 7;
    float v = 0.5f * cospif((float)((2 * j + 1) * i) / 16.f);
    if (i == 0) v *= 0.7071067811865476f;
    D[tid] = v;
}

__global__ void wsum_k(const float* __restrict__ wd1, float* __restrict__ wd1s) {
    int tid = blockIdx.x * blockDim.x + threadIdx.x;
    if (tid >= 288) return;
    int o = tid / 9, r = tid % 9;
    wd1s[tid] = wd1[(o * 3 + 0) * 9 + r] + wd1[(o * 3 + 1) * 9 + r] + wd1[(o * 3 + 2) * 9 + r];
}

__global__ void dct_mean_k(const float* __restrict__ x, const float* __restrict__ D,
                           float* __restrict__ dctimg)
{
    __shared__ float part[8][64];
    __shared__ float Mb[64];
    __shared__ float T[64];
    int b = blockIdx.x;
    int tid = threadIdx.x;            // 512
    int ij = tid & 63, ch = tid >> 6;
    int i = ij >> 3, j = ij & 7;
    const float* xb = x + (long long)b * 3 * HW;
    float s = 0.f;
    for (int blk = ch; blk < 784; blk += 8) {
        int m = blk / 28, n = blk % 28;
        int idx = (m * 8 + i) * IMG + (n * 8 + j);
        s += 0.299f * xb[idx] + 0.587f * xb[idx + HW] + 0.114f * xb[idx + 2 * HW];
    }
    part[ch][ij] = s;
    __syncthreads();
    if (tid < 64) {
        float t = 0.f;
        for (int c = 0; c < 8; c++) t += part[c][tid];
        Mb[tid] = t * (255.f / 784.f);
    }
    __syncthreads();
    if (tid < 64) {
        float t = 0.f;
        for (int k = 0; k < 8; k++) t += D[i * 8 + k] * Mb[k * 8 + j];
        T[tid] = t;
    }
    __syncthreads();
    if (tid < 64) {
        float o = 0.f;
        for (int k = 0; k < 8; k++) o += T[i * 8 + k] * D[j * 8 + k];
        dctimg[b * 64 + tid] = o;
    }
}

__global__ void resize_k(const float* __restrict__ dctimg, float* __restrict__ out) {
    int gid = blockIdx.x * blockDim.x + threadIdx.x;
    if (gid >= BATCH * HW) return;
    int ow = gid % IMG;
    int t = gid / IMG;
    int oh = t % IMG;
    int b = t / IMG;
    float fh = (oh + 0.5f) * (8.f / 224.f) - 0.5f;
    float fw = (ow + 0.5f) * (8.f / 224.f) - 0.5f;
    fh = fminf(fmaxf(fh, 0.f), 7.f);
    fw = fminf(fmaxf(fw, 0.f), 7.f);
    int h0 = (int)floorf(fh), w0 = (int)floorf(fw);
    int h1 = min(h0 + 1, 7), w1 = min(w0 + 1, 7);
    float ah = fh - (float)h0, aw = fw - (float)w0;
    const float* d = dctimg + b * 64;
    float v00 = d[h0 * 8 + w0], v01 = d[h0 * 8 + w1];
    float v10 = d[h1 * 8 + w0], v11 = d[h1 * 8 + w1];
    out[gid] = (1.f - ah) * ((1.f - aw) * v00 + aw * v01) + ah * ((1.f - aw) * v10 + aw * v11);
}

__global__ void transpose224_k(const float* __restrict__ src, float* __restrict__ dst) {
    __shared__ float tile[32][33];
    int m = blockIdx.z;
    const float* s = src + (long long)m * HW;
    float* d = dst + (long long)m * HW;
    int i0 = blockIdx.y * 32, j0 = blockIdx.x * 32;
    int tx = threadIdx.x, ty = threadIdx.y;
    tile[ty][tx] = s[(i0 + ty) * IMG + (j0 + tx)];
    __syncthreads();
    d[(j0 + ty) * IMG + (i0 + tx)] = tile[tx][ty];
}

__global__ void fftin_k(const float* __restrict__ G, float* __restrict__ fftin, int p) {
    __shared__ float tile[32][33];
    int m = blockIdx.z;          // 0..191
    int b = m / 3, c = m % 3;
    const float* s = G + (long long)m * HW;
    float* d = fftin + ((long long)(2 * c + p) * BATCH + b) * HW;
    int i0 = blockIdx.y * 32, j0 = blockIdx.x * 32;
    int tx = threadIdx.x, ty = threadIdx.y;
    tile[ty][tx] = s[(i0 + ty) * IMG + (j0 + tx)];
    __syncthreads();
    d[(j0 + ty) * IMG + (i0 + tx)] = tile[tx][ty];
}

__global__ void pool7_k(const float* __restrict__ src, float* __restrict__ pooled, int base) {
    int gid = blockIdx.x * blockDim.x + threadIdx.x;
    if (gid >= 64 * BATCH * 49) return;
    int j = gid % 7;
    int t = gid / 7;
    int i = t % 7;
    t /= 7;
    int c = t % 64;
    int b = t / 64;
    const float* s = src + ((long long)c * BATCH + b) * 56 * 56;
    float acc = 0.f;
#pragma unroll
    for (int p = 0; p < 8; p++)
#pragma unroll
        for (int q = 0; q < 8; q++)
            acc += s[(i * 8 + p) * 56 + (j * 8 + q)];
    pooled[b * 6272 + base + c * 49 + i * 7 + j] = acc * (1.f / 64.f);
}

__global__ void gap_k(const float* __restrict__ h3, float* __restrict__ comb) {
    int gid = blockIdx.x * blockDim.x + threadIdx.x;
    if (gid >= 512 * BATCH) return;
    int c = gid / BATCH, b = gid % BATCH;
    const float* s = h3 + ((long long)c * BATCH + b) * 196;
    float acc = 0.f;
    for (int t = 0; t < 196; t++) acc += s[t];
    comb[b * 1024 + c] = acc * (1.f / 196.f);
}

__global__ void cls_k(const float* __restrict__ fused, const float* __restrict__ Wc,
                      const float* __restrict__ bc, const float* __restrict__ temp,
                      float* __restrict__ out)
{
    int tid = threadIdx.x; // 128
    if (tid >= 128) return;
    int b = tid >> 1, j = tid & 1;
    float s = bc[j];
    const float* f = fused + b * 512;
    for (int k = 0; k < 512; k++) s += f[k] * Wc[k * 2 + j];
    out[b * 2 + j] = s;
    out[128 + b * 2 + j] = s / temp[0];
}

// ---------------------------------------------------------------------------
// Host launchers
// ---------------------------------------------------------------------------
static void run_sgemm(const float* A, const float* B, float* C, int M, int N, int K,
                      const float* biasN, int relu,
                      float alpha = 1.f, float beta = 0.f, int ldc = -1)
{
    if (ldc < 0) ldc = N;
    dim3 grid((N + 127) / 128, (M + 127) / 128);
    sgemm_k<<<grid, 256>>>(A, B, C, M, N, K, ldc, alpha, beta, biasN, relu);
}

static void run_conv(const float* src, const float* Wt, const float* bias, float* dst,
                     int Co, int Ci, int H, int W, int OH, int OW,
                     int KH, int KW, int stride, int pad,
                     long long sC, long long sB)
{
    int Ntot = BATCH * OH * OW;
    int K = Ci * KH * KW;
    if (Co >= 128) {
        dim3 grid((Ntot + 127) / 128, (Co + 127) / 128);
        conv_igemm_k<8><<<grid, 256>>>(src, Wt, bias, dst, Co, K, H, W, OH, OW,
                                       KH, KW, stride, pad, sC, sB, Ntot);
    } else if (Co >= 64) {
        dim3 grid((Ntot + 127) / 128, (Co + 63) / 64);
        conv_igemm_k<4><<<grid, 256>>>(src, Wt, bias, dst, Co, K, H, W, OH, OW,
                                       KH, KW, stride, pad, sC, sB, Ntot);
    } else {
        dim3 grid((Ntot + 127) / 128, (Co + 31) / 32);
        conv_igemm_k<2><<<grid, 256>>>(src, Wt, bias, dst, Co, K, H, W, OH, OW,
                                       KH, KW, stride, pad, sC, sB, Ntot);
    }
}

extern "C" void kernel_launch(void* const* d_in, const int* in_sizes, int n_in,
                              void* d_out, int out_size)
{
    const float* x      = (const float*)d_in[0];
    const float* w_stem = (const float*)d_in[1];
    const float* b_stem = (const float*)d_in[2];
    const float* w1     = (const float*)d_in[3];
    const float* b1     = (const float*)d_in[4];
    const float* w2     = (const float*)d_in[5];
    const float* b2     = (const float*)d_in[6];
    const float* w3     = (const float*)d_in[7];
    const float* b3     = (const float*)d_in[8];
    const float* wd1    = (const float*)d_in[9];
    const float* bd1    = (const float*)d_in[10];
    const float* wd2    = (const float*)d_in[11];
    const float* bd2    = (const float*)d_in[12];
    const float* wf1    = (const float*)d_in[13];
    const float* bf1    = (const float*)d_in[14];
    const float* wf2    = (const float*)d_in[15];
    const float* bf2    = (const float*)d_in[16];
    const float* W_freq = (const float*)d_in[17];
    const float* b_freq = (const float*)d_in[18];
    const float* W_fu1  = (const float*)d_in[19];
    const float* b_fu1  = (const float*)d_in[20];
    const float* W_fu2  = (const float*)d_in[21];
    const float* b_fu2  = (const float*)d_in[22];
    const float* W_cls  = (const float*)d_in[23];
    const float* b_cls  = (const float*)d_in[24];
    const float* temp   = (const float*)d_in[25];
    float* out = (float*)d_out;

    float *h0, *h1, *h2, *h3, *hd1, *hd2, *hf1, *hf2;
    float *dctimg, *dctres, *wd1s, *Wre, *Wim, *D8;
    float *Zre, *Zim, *Ztre, *Ztim, *Gre, *Gim, *fftin;
    float *pooled, *comb, *buf1, *fused;
    cudaGetSymbolAddress((void**)&h0, g_h0);
    cudaGetSymbolAddress((void**)&h1, g_h1);
    cudaGetSymbolAddress((void**)&h2, g_h2);
    cudaGetSymbolAddress((void**)&h3, g_h3);
    cudaGetSymbolAddress((void**)&hd1, g_hd1);
    cudaGetSymbolAddress((void**)&hd2, g_hd2);
    cudaGetSymbolAddress((void**)&hf1, g_hf1);
    cudaGetSymbolAddress((void**)&hf2, g_hf2);
    cudaGetSymbolAddress((void**)&dctimg, g_dctimg);
    cudaGetSymbolAddress((void**)&dctres, g_dctres);
    cudaGetSymbolAddress((void**)&wd1s, g_wd1s);
    cudaGetSymbolAddress((void**)&Wre, g_Wre);
    cudaGetSymbolAddress((void**)&Wim, g_Wim);
    cudaGetSymbolAddress((void**)&D8, g_D8);
    cudaGetSymbolAddress((void**)&Zre, g_Zre);
    cudaGetSymbolAddress((void**)&Zim, g_Zim);
    cudaGetSymbolAddress((void**)&Ztre, g_Ztre);
    cudaGetSymbolAddress((void**)&Ztim, g_Ztim);
    cudaGetSymbolAddress((void**)&Gre, g_Gre);
    cudaGetSymbolAddress((void**)&Gim, g_Gim);
    cudaGetSymbolAddress((void**)&fftin, g_fftin);
    cudaGetSymbolAddress((void**)&pooled, g_pooled);
    cudaGetSymbolAddress((void**)&comb, g_comb);
    cudaGetSymbolAddress((void**)&buf1, g_buf1);
    cudaGetSymbolAddress((void**)&fused, g_fused);

    // ---- init constants ----
    genW_k<<<(HW + 255) / 256, 256>>>(Wre, Wim);
    genD8_k<<<1, 64>>>(D8);
    wsum_k<<<2, 256>>>(wd1, wd1s);

    // ---- CNN backbone (implicit GEMM convs) ----
    // stem: 3->64, 7x7, s2, pad 2; x layout [B][3][224][224]
    run_conv(x, w_stem, b_stem, h0, 64, 3, 224, 224, 112, 112, 7, 7, 2, 2,
             (long long)HW, 3LL * HW);
    // conv1: 64->128, 3x3, s2, pad 0; h0 layout [64][B][112][112]
    run_conv(h0, w1, b1, h1, 128, 64, 112, 112, 56, 56, 3, 3, 2, 0,
             64LL * 112 * 112, 112LL * 112);
    // conv2: 128->256, 56->28
    run_conv(h1, w2, b2, h2, 256, 128, 56, 56, 28, 28, 3, 3, 2, 0,
             64LL * 56 * 56, 56LL * 56);
    // conv3: 256->512, 28->14
    run_conv(h2, w3, b3, h3, 512, 256, 28, 28, 14, 14, 3, 3, 2, 0,
             64LL * 28 * 28, 28LL * 28);
    gap_k<<<(512 * BATCH + 255) / 256, 256>>>(h3, comb);

    // ---- DCT branch ----
    dct_mean_k<<<BATCH, 512>>>(x, D8, dctimg);
    resize_k<<<(BATCH * HW + 255) / 256, 256>>>(dctimg, dctres);
    // wd1 folded to 1 input channel: 1->32, 224->112; dctres [B][224][224]
    run_conv(dctres, wd1s, bd1, hd1, 32, 1, 224, 224, 112, 112, 3, 3, 2, 0,
             0LL, (long long)HW);
    // wd2: 32->64, 112->56
    run_conv(hd1, wd2, bd2, hd2, 64, 32, 112, 112, 56, 56, 3, 3, 2, 0,
             64LL * 112 * 112, 112LL * 112);
    pool7_k<<<(64 * BATCH * 49 + 255) / 256, 256>>>(hd2, pooled, 0);

    // ---- FFT branch (DFT as matmul) ----
    run_sgemm(x, Wre, Zre, 43008, 224, 224, nullptr, 0);
    run_sgemm(x, Wim, Zim, 43008, 224, 224, nullptr, 0);
    {
        dim3 tgrid(7, 7, 192), tblk(32, 32);
        transpose224_k<<<tgrid, tblk>>>(Zre, Ztre);
        transpose224_k<<<tgrid, tblk>>>(Zim, Ztim);
    }
    run_sgemm(Ztre, Wre, Gre, 43008, 224, 224, nullptr, 0, 1.f, 0.f);
    run_sgemm(Ztim, Wim, Gre, 43008, 224, 224, nullptr, 0, -1.f, 1.f);
    run_sgemm(Ztre, Wim, Gim, 43008, 224, 224, nullptr, 0, 1.f, 0.f);
    run_sgemm(Ztim, Wre, Gim, 43008, 224, 224, nullptr, 0, 1.f, 1.f);
    {
        dim3 tgrid(7, 7, 192), tblk(32, 32);
        fftin_k<<<tgrid, tblk>>>(Gre, fftin, 0);
        fftin_k<<<tgrid, tblk>>>(Gim, fftin, 1);
    }
    // wf1: 6->32, 224->112; fftin layout [6][B][224][224]
    run_conv(fftin, wf1, bf1, hf1, 32, 6, 224, 224, 112, 112, 3, 3, 2, 0,
             (long long)BATCH * HW, (long long)HW);
    // wf2: 32->64, 112->56
    run_conv(hf1, wf2, bf2, hf2, 64, 32, 112, 112, 56, 56, 3, 3, 2, 0,
             64LL * 112 * 112, 112LL * 112);
    pool7_k<<<(64 * BATCH * 49 + 255) / 256, 256>>>(hf2, pooled, 3136);

    // ---- fusion + classifier ----
    run_sgemm(pooled, W_freq, comb + 512, 64, 512, 6272, b_freq, 1, 1.f, 0.f, 1024);
    run_sgemm(comb, W_fu1, buf1, 64, 1024, 1024, b_fu1, 1);
    run_sgemm(buf1, W_fu2, fused, 64, 512, 1024, b_fu2, 1);
    cls_k<<<1, 128>>>(fused, W_cls, b_cls, temp, out);
}

// round 3
// speedup vs baseline: 1.2082x; 1.0654x over previous
#include <cuda_runtime.h>
#include <cuda_bf16.h>
#include <math.h>

#define BATCH 64
#define IMG 224
#define HW  (IMG*IMG)          // 50176

__device__ float g_h0[64LL*64*112*112];
__device__ float g_h1[128LL*64*56*56];
__device__ float g_h2[256LL*64*28*28];
__device__ float g_h3[512LL*64*14*14];
__device__ float g_hd1[32LL*64*112*112];
__device__ float g_hd2[64LL*64*56*56];
__device__ float g_hf1[32LL*64*112*112];
__device__ float g_hf2[64LL*64*56*56];
__device__ float g_dctimg[BATCH*64];
__device__ float g_dctres[BATCH*HW];
__device__ float g_wd1s[32*9];
__device__ float g_Wre[HW];
__device__ float g_Wim[HW];
__device__ float g_D8[64];
__device__ float g_Zre[43008LL*224];
__device__ float g_Zim[43008LL*224];
__device__ float g_Ztre[43008LL*224];
__device__ float g_Ztim[43008LL*224];
__device__ float g_Gre[43008LL*224];
__device__ float g_Gim[43008LL*224];
__device__ float g_fftin[6LL*BATCH*HW];
__device__ float g_pooled[BATCH*6272];
__device__ float g_comb[BATCH*1024];
__device__ float g_buf1[BATCH*1024];
__device__ float g_fused[BATCH*512];

// ---------------------------------------------------------------------------
// Direct stride-2 conv with parity-split smem staging.
// Template: KH,KW (taps), P (padded even/odd row pitch = OW + KW/2 + 2),
//           RM (rows per thread; TM = 16*RM output channels per block).
// Grid: (ceil(OH*OW/128), Co/TM, BATCH). Block: 256 threads.
// Output layout: dst[co][b][oh][ow]. Input: src + c*sC + b*sB + ih*W + iw.
// ---------------------------------------------------------------------------
template<int KH, int KW, int P, int RM>
__global__ void __launch_bounds__(256) dconv_k(
    const float* __restrict__ src, const float* __restrict__ Wt,
    const float* __restrict__ bias, float* __restrict__ dst,
    int Ci, int H, int W, int OHOW, int padh, int padw,
    long long sC, long long sB)
{
    constexpr int OW = P - (KW / 2) - 2;
    constexpr int NR = 126 / OW + 2;            // max output rows spanned by 128 outputs
    constexpr int R  = 2 * (NR - 1) + KH;       // staged input rows
    constexpr int TM = 16 * RM;
    constexpr int KK = KH * KW;

    __shared__ float As[KK * TM];
    __shared__ float Sb[2 * R * P];             // [even | odd], each R*P

    int tid = threadIdx.x;
    int tx = tid & 15, ty = tid >> 4;
    int row0 = blockIdx.y * TM;
    int bz = blockIdx.z;
    int s0 = blockIdx.x * 128;
    int oh_lo = s0 / OW;
    int base_ih = 2 * oh_lo - padh;
    const float* sp = src + bz * sB;

    // per-thread output column precompute (lane-strided mapping: n = j*16 + tx)
    int pbase[8];
    unsigned okmask = 0;
#pragma unroll
    for (int j = 0; j < 8; j++) {
        int s = s0 + j * 16 + tx;
        if (s < OHOW) okmask |= (1u << j);
        int sc = (s < OHOW) ? s : (OHOW - 1);
        int oh = sc / OW;
        int ow = sc - oh * OW;
        pbase[j] = 2 * (oh - oh_lo) * P + ow;
    }

    float acc[RM][8];
#pragma unroll
    for (int i = 0; i < RM; i++)
#pragma unroll
        for (int j = 0; j < 8; j++) acc[i][j] = 0.f;

    for (int c = 0; c < Ci; c++) {
        // stage weights for this channel: As[tap*TM + m]
        for (int t = tid; t < KK * TM; t += 256) {
            int m = t / KK, tap = t - m * KK;
            As[tap * TM + m] = Wt[(long long)(row0 + m) * (Ci * KK) + c * KK + tap];
        }
        // stage input rows, parity-split (coalesced gmem reads)
        {
            const float* cp = sp + c * sC;
            for (int t = tid; t < R * 2 * P; t += 256) {
                int r = t / (2 * P);
                int u = t - r * 2 * P;
                int ih = base_ih + r;
                int ic = u - padw;
                float v = 0.f;
                if ((unsigned)ih < (unsigned)H && (unsigned)ic < (unsigned)W)
                    v = cp[(long long)ih * W + ic];
                Sb[(u & 1) * (R * P) + r * P + (u >> 1)] = v;
            }
        }
        __syncthreads();

        // compute: unrolled taps
#pragma unroll
        for (int kh = 0; kh < KH; kh++) {
#pragma unroll
            for (int kw = 0; kw < KW; kw++) {
                const float* bb = Sb + (kw & 1) * (R * P) + kh * P + (kw >> 1);
                float a[RM];
                if constexpr (RM == 8) {
                    *(float4*)&a[0] = *(const float4*)&As[(kh * KW + kw) * TM + ty * 8];
                    *(float4*)&a[4] = *(const float4*)&As[(kh * KW + kw) * TM + ty * 8 + 4];
                } else if constexpr (RM == 4) {
                    *(float4*)&a[0] = *(const float4*)&As[(kh * KW + kw) * TM + ty * 4];
                } else {
                    *(float2*)&a[0] = *(const float2*)&As[(kh * KW + kw) * TM + ty * 2];
                }
#pragma unroll
                for (int j = 0; j < 8; j++) {
                    float bv = bb[pbase[j]];
#pragma unroll
                    for (int i = 0; i < RM; i++) acc[i][j] += a[i] * bv;
                }
            }
        }
        __syncthreads();
    }

    // epilogue
    long long NtotG = (long long)BATCH * OHOW;
#pragma unroll
    for (int i = 0; i < RM; i++) {
        int gm = row0 + ty * RM + i;
        float bm = bias[gm];
        float* drow = dst + (long long)gm * NtotG + (long long)bz * OHOW;
#pragma unroll
        for (int j = 0; j < 8; j++) {
            if (okmask & (1u << j)) {
                int s = s0 + j * 16 + tx;
                drow[s] = fmaxf(acc[i][j] + bm, 0.f);
            }
        }
    }
}

// ---------------------------------------------------------------------------
// Dense SGEMM (DFT + FC): C = alpha*A*B + beta*C + biasN (+relu)
// ---------------------------------------------------------------------------
__global__ void __launch_bounds__(256) sgemm_k(
    const float* __restrict__ A, const float* __restrict__ B, float* __restrict__ C,
    int M, int N, int K, int ldc, float alpha, float beta,
    const float* __restrict__ biasN, int relu)
{
    __shared__ float As[8][128];
    __shared__ float Bs[8][128];
    int tid = threadIdx.x;
    int tx = tid & 15, ty = tid >> 4;
    int row0 = blockIdx.y * 128, col0 = blockIdx.x * 128;

    float acc[8][8];
#pragma unroll
    for (int i = 0; i < 8; i++)
#pragma unroll
        for (int j = 0; j < 8; j++) acc[i][j] = 0.f;

    for (int k0 = 0; k0 < K; k0 += 8) {
#pragma unroll
        for (int i = 0; i < 4; i++) {
            int idx = tid + i * 256;
            int m = idx >> 3, kk = idx & 7;
            int gm = row0 + m, gk = k0 + kk;
            float v = 0.f;
            if (gm < M && gk < K) v = A[(long long)gm * K + gk];
            As[kk][m] = v;
        }
#pragma unroll
        for (int i = 0; i < 4; i++) {
            int idx = tid + i * 256;
            int kk = idx >> 7, nn = idx & 127;
            int gn = col0 + nn, gk = k0 + kk;
            float v = 0.f;
            if (gk < K && gn < N) v = B[(long long)gk * N + gn];
            Bs[kk][nn] = v;
        }
        __syncthreads();
#pragma unroll
        for (int kk = 0; kk < 8; kk++) {
            float a[8], b[8];
            *(float4*)&a[0] = *(const float4*)&As[kk][ty * 8];
            *(float4*)&a[4] = *(const float4*)&As[kk][ty * 8 + 4];
            *(float4*)&b[0] = *(const float4*)&Bs[kk][tx * 8];
            *(float4*)&b[4] = *(const float4*)&Bs[kk][tx * 8 + 4];
#pragma unroll
            for (int i = 0; i < 8; i++)
#pragma unroll
                for (int j = 0; j < 8; j++) acc[i][j] += a[i] * b[j];
        }
        __syncthreads();
    }

#pragma unroll
    for (int i = 0; i < 8; i++) {
        int gm = row0 + ty * 8 + i;
        if (gm >= M) continue;
#pragma unroll
        for (int j = 0; j < 8; j++) {
            int gn = col0 + tx * 8 + j;
            if (gn >= N) continue;
            float v = alpha * acc[i][j];
            if (beta != 0.f) v += beta * C[(long long)gm * ldc + gn];
            if (biasN) v += biasN[gn];
            if (relu) v = fmaxf(v, 0.f);
            C[(long long)gm * ldc + gn] = v;
        }
    }
}

// ---------------------------------------------------------------------------
// Small kernels
// ---------------------------------------------------------------------------
__global__ void genW_k(float* Wre, float* Wim) {
    int gid = blockIdx.x * blockDim.x + threadIdx.x;
    if (gid >= HW) return;
    int j = gid / IMG, k = gid % IMG;
    int r = (j * k) % IMG;
    float a = 2.f * (float)r / (float)IMG;
    Wre[gid] = cospif(a);
    Wim[gid] = -sinpif(a);
}

__global__ void genD8_k(float* D) {
    int tid = threadIdx.x;
    if (tid >= 64) return;
    int i = tid >> 3, j = tid & 7;
    float v = 0.5f * cospif((float)((2 * j + 1) * i) / 16.f);
    if (i == 0) v *= 0.7071067811865476f;
    D[tid] = v;
}

__global__ void wsum_k(const float* __restrict__ wd1, float* __restrict__ wd1s) {
    int tid = blockIdx.x * blockDim.x + threadIdx.x;
    if (tid >= 288) return;
    int o = tid / 9, r = tid % 9;
    wd1s[tid] = wd1[(o * 3 + 0) * 9 + r] + wd1[(o * 3 + 1) * 9 + r] + wd1[(o * 3 + 2) * 9 + r];
}

__global__ void dct_mean_k(const float* __restrict__ x, const float* __restrict__ D,
                           float* __restrict__ dctimg)
{
    __shared__ float part[8][64];
    __shared__ float Mb[64];
    __shared__ float T[64];
    int b = blockIdx.x;
    int tid = threadIdx.x;            // 512
    int ij = tid & 63, ch = tid >> 6;
    int i = ij >> 3, j = ij & 7;
    const float* xb = x + (long long)b * 3 * HW;
    float s = 0.f;
    for (int blk = ch; blk < 784; blk += 8) {
        int m = blk / 28, n = blk % 28;
        int idx = (m * 8 + i) * IMG + (n * 8 + j);
        s += 0.299f * xb[idx] + 0.587f * xb[idx + HW] + 0.114f * xb[idx + 2 * HW];
    }
    part[ch][ij] = s;
    __syncthreads();
    if (tid < 64) {
        float t = 0.f;
        for (int c = 0; c < 8; c++) t += part[c][tid];
        Mb[tid] = t * (255.f / 784.f);
    }
    __syncthreads();
    if (tid < 64) {
        float t = 0.f;
        for (int k = 0; k < 8; k++) t += D[i * 8 + k] * Mb[k * 8 + j];
        T[tid] = t;
    }
    __syncthreads();
    if (tid < 64) {
        float o = 0.f;
        for (int k = 0; k < 8; k++) o += T[i * 8 + k] * D[j * 8 + k];
        dctimg[b * 64 + tid] = o;
    }
}

__global__ void resize_k(const float* __restrict__ dctimg, float* __restrict__ out) {
    int gid = blockIdx.x * blockDim.x + threadIdx.x;
    if (gid >= BATCH * HW) return;
    int ow = gid % IMG;
    int t = gid / IMG;
    int oh = t % IMG;
    int b = t / IMG;
    float fh = (oh + 0.5f) * (8.f / 224.f) - 0.5f;
    float fw = (ow + 0.5f) * (8.f / 224.f) - 0.5f;
    fh = fminf(fmaxf(fh, 0.f), 7.f);
    fw = fminf(fmaxf(fw, 0.f), 7.f);
    int h0 = (int)floorf(fh), w0 = (int)floorf(fw);
    int h1 = min(h0 + 1, 7), w1 = min(w0 + 1, 7);
    float ah = fh - (float)h0, aw = fw - (float)w0;
    const float* d = dctimg + b * 64;
    float v00 = d[h0 * 8 + w0], v01 = d[h0 * 8 + w1];
    float v10 = d[h1 * 8 + w0], v11 = d[h1 * 8 + w1];
    out[gid] = (1.f - ah) * ((1.f - aw) * v00 + aw * v01) + ah * ((1.f - aw) * v10 + aw * v11);
}

__global__ void transpose224_k(const float* __restrict__ src, float* __restrict__ dst) {
    __shared__ float tile[32][33];
    int m = blockIdx.z;
    const float* s = src + (long long)m * HW;
    float* d = dst + (long long)m * HW;
    int i0 = blockIdx.y * 32, j0 = blockIdx.x * 32;
    int tx = threadIdx.x, ty = threadIdx.y;
    tile[ty][tx] = s[(i0 + ty) * IMG + (j0 + tx)];
    __syncthreads();
    d[(j0 + ty) * IMG + (i0 + tx)] = tile[tx][ty];
}

__global__ void fftin_k(const float* __restrict__ G, float* __restrict__ fftin, int p) {
    __shared__ float tile[32][33];
    int m = blockIdx.z;          // 0..191
    int b = m / 3, c = m % 3;
    const float* s = G + (long long)m * HW;
    float* d = fftin + ((long long)(2 * c + p) * BATCH + b) * HW;
    int i0 = blockIdx.y * 32, j0 = blockIdx.x * 32;
    int tx = threadIdx.x, ty = threadIdx.y;
    tile[ty][tx] = s[(i0 + ty) * IMG + (j0 + tx)];
    __syncthreads();
    d[(j0 + ty) * IMG + (i0 + tx)] = tile[tx][ty];
}

__global__ void pool7_k(const float* __restrict__ src, float* __restrict__ pooled, int base) {
    int gid = blockIdx.x * blockDim.x + threadIdx.x;
    if (gid >= 64 * BATCH * 49) return;
    int j = gid % 7;
    int t = gid / 7;
    int i = t % 7;
    t /= 7;
    int c = t % 64;
    int b = t / 64;
    const float* s = src + ((long long)c * BATCH + b) * 56 * 56;
    float acc = 0.f;
#pragma unroll
    for (int p = 0; p < 8; p++)
#pragma unroll
        for (int q = 0; q < 8; q++)
            acc += s[(i * 8 + p) * 56 + (j * 8 + q)];
    pooled[b * 6272 + base + c * 49 + i * 7 + j] = acc * (1.f / 64.f);
}

__global__ void gap_k(const float* __restrict__ h3, float* __restrict__ comb) {
    int gid = blockIdx.x * blockDim.x + threadIdx.x;
    if (gid >= 512 * BATCH) return;
    int c = gid / BATCH, b = gid % BATCH;
    const float* s = h3 + ((long long)c * BATCH + b) * 196;
    float acc = 0.f;
    for (int t = 0; t < 196; t++) acc += s[t];
    comb[b * 1024 + c] = acc * (1.f / 196.f);
}

__global__ void cls_k(const float* __restrict__ fused, const float* __restrict__ Wc,
                      const float* __restrict__ bc, const float* __restrict__ temp,
                      float* __restrict__ out)
{
    int tid = threadIdx.x; // 128
    if (tid >= 128) return;
    int b = tid >> 1, j = tid & 1;
    float s = bc[j];
    const float* f = fused + b * 512;
    for (int k = 0; k < 512; k++) s += f[k] * Wc[k * 2 + j];
    out[b * 2 + j] = s;
    out[128 + b * 2 + j] = s / temp[0];
}

// ---------------------------------------------------------------------------
static void run_sgemm(const float* A, const float* B, float* C, int M, int N, int K,
                      const float* biasN, int relu,
                      float alpha = 1.f, float beta = 0.f, int ldc = -1)
{
    if (ldc < 0) ldc = N;
    dim3 grid((N + 127) / 128, (M + 127) / 128);
    sgemm_k<<<grid, 256>>>(A, B, C, M, N, K, ldc, alpha, beta, biasN, relu);
}

extern "C" void kernel_launch(void* const* d_in, const int* in_sizes, int n_in,
                              void* d_out, int out_size)
{
    const float* x      = (const float*)d_in[0];
    const float* w_stem = (const float*)d_in[1];
    const float* b_stem = (const float*)d_in[2];
    const float* w1     = (const float*)d_in[3];
    const float* b1     = (const float*)d_in[4];
    const float* w2     = (const float*)d_in[5];
    const float* b2     = (const float*)d_in[6];
    const float* w3     = (const float*)d_in[7];
    const float* b3     = (const float*)d_in[8];
    const float* wd1    = (const float*)d_in[9];
    const float* bd1    = (const float*)d_in[10];
    const float* wd2    = (const float*)d_in[11];
    const float* bd2    = (const float*)d_in[12];
    const float* wf1    = (const float*)d_in[13];
    const float* bf1    = (const float*)d_in[14];
    const float* wf2    = (const float*)d_in[15];
    const float* bf2    = (const float*)d_in[16];
    const float* W_freq = (const float*)d_in[17];
    const float* b_freq = (const float*)d_in[18];
    const float* W_fu1  = (const float*)d_in[19];
    const float* b_fu1  = (const float*)d_in[20];
    const float* W_fu2  = (const float*)d_in[21];
    const float* b_fu2  = (const float*)d_in[22];
    const float* W_cls  = (const float*)d_in[23];
    const float* b_cls  = (const float*)d_in[24];
    const float* temp   = (const float*)d_in[25];
    float* out = (float*)d_out;

    float *h0, *h1, *h2, *h3, *hd1, *hd2, *hf1, *hf2;
    float *dctimg, *dctres, *wd1s, *Wre, *Wim, *D8;
    float *Zre, *Zim, *Ztre, *Ztim, *Gre, *Gim, *fftin;
    float *pooled, *comb, *buf1, *fused;
    cudaGetSymbolAddress((void**)&h0, g_h0);
    cudaGetSymbolAddress((void**)&h1, g_h1);
    cudaGetSymbolAddress((void**)&h2, g_h2);
    cudaGetSymbolAddress((void**)&h3, g_h3);
    cudaGetSymbolAddress((void**)&hd1, g_hd1);
    cudaGetSymbolAddress((void**)&hd2, g_hd2);
    cudaGetSymbolAddress((void**)&hf1, g_hf1);
    cudaGetSymbolAddress((void**)&hf2, g_hf2);
    cudaGetSymbolAddress((void**)&dctimg, g_dctimg);
    cudaGetSymbolAddress((void**)&dctres, g_dctres);
    cudaGetSymbolAddress((void**)&wd1s, g_wd1s);
    cudaGetSymbolAddress((void**)&Wre, g_Wre);
    cudaGetSymbolAddress((void**)&Wim, g_Wim);
    cudaGetSymbolAddress((void**)&D8, g_D8);
    cudaGetSymbolAddress((void**)&Zre, g_Zre);
    cudaGetSymbolAddress((void**)&Zim, g_Zim);
    cudaGetSymbolAddress((void**)&Ztre, g_Ztre);
    cudaGetSymbolAddress((void**)&Ztim, g_Ztim);
    cudaGetSymbolAddress((void**)&Gre, g_Gre);
    cudaGetSymbolAddress((void**)&Gim, g_Gim);
    cudaGetSymbolAddress((void**)&fftin, g_fftin);
    cudaGetSymbolAddress((void**)&pooled, g_pooled);
    cudaGetSymbolAddress((void**)&comb, g_comb);
    cudaGetSymbolAddress((void**)&buf1, g_buf1);
    cudaGetSymbolAddress((void**)&fused, g_fused);

    // ---- init constants ----
    genW_k<<<(HW + 255) / 256, 256>>>(Wre, Wim);
    genD8_k<<<1, 64>>>(D8);
    wsum_k<<<2, 256>>>(wd1, wd1s);

    // ---- CNN backbone (direct convs) ----
    // stem: 3->64, 7x7, s2, pad(2,2 begin); OW=112 -> P=117, RM=4 (TM=64)
    dconv_k<7,7,117,4><<<dim3(98, 1, BATCH), 256>>>(
        x, w_stem, b_stem, h0, 3, 224, 224, 12544, 2, 2, (long long)HW, 3LL * HW);
    // conv1: 64->128, 3x3 s2 pad0, 112->56; P=59, RM=8
    dconv_k<3,3,59,8><<<dim3(25, 1, BATCH), 256>>>(
        h0, w1, b1, h1, 64, 112, 112, 3136, 0, 0, 64LL * 12544, 12544LL);
    // conv2: 128->256, 56->28; P=31
    dconv_k<3,3,31,8><<<dim3(7, 2, BATCH), 256>>>(
        h1, w2, b2, h2, 128, 56, 56, 784, 0, 0, 64LL * 3136, 3136LL);
    // conv3: 256->512, 28->14; P=17
    dconv_k<3,3,17,8><<<dim3(2, 4, BATCH), 256>>>(
        h2, w3, b3, h3, 256, 28, 28, 196, 0, 0, 64LL * 784, 784LL);
    gap_k<<<(512 * BATCH + 255) / 256, 256>>>(h3, comb);

    // ---- DCT branch ----
    dct_mean_k<<<BATCH, 512>>>(x, D8, dctimg);
    resize_k<<<(BATCH * HW + 255) / 256, 256>>>(dctimg, dctres);
    // wd1 (folded, 1 ch): 1->32, 224->112; P=115, RM=2 (TM=32)
    dconv_k<3,3,115,2><<<dim3(98, 1, BATCH), 256>>>(
        dctres, wd1s, bd1, hd1, 1, 224, 224, 12544, 0, 0, 0LL, (long long)HW);
    // wd2: 32->64, 112->56; P=59, RM=4
    dconv_k<3,3,59,4><<<dim3(25, 1, BATCH), 256>>>(
        hd1, wd2, bd2, hd2, 32, 112, 112, 3136, 0, 0, 64LL * 12544, 12544LL);
    pool7_k<<<(64 * BATCH * 49 + 255) / 256, 256>>>(hd2, pooled, 0);

    // ---- FFT branch (DFT as matmul) ----
    run_sgemm(x, Wre, Zre, 43008, 224, 224, nullptr, 0);
    run_sgemm(x, Wim, Zim, 43008, 224, 224, nullptr, 0);
    {
        dim3 tgrid(7, 7, 192), tblk(32, 32);
        transpose224_k<<<tgrid, tblk>>>(Zre, Ztre);
        transpose224_k<<<tgrid, tblk>>>(Zim, Ztim);
    }
    run_sgemm(Ztre, Wre, Gre, 43008, 224, 224, nullptr, 0, 1.f, 0.f);
    run_sgemm(Ztim, Wim, Gre, 43008, 224, 224, nullptr, 0, -1.f, 1.f);
    run_sgemm(Ztre, Wim, Gim, 43008, 224, 224, nullptr, 0, 1.f, 0.f);
    run_sgemm(Ztim, Wre, Gim, 43008, 224, 224, nullptr, 0, 1.f, 1.f);
    {
        dim3 tgrid(7, 7, 192), tblk(32, 32);
        fftin_k<<<tgrid, tblk>>>(Gre, fftin, 0);
        fftin_k<<<tgrid, tblk>>>(Gim, fftin, 1);
    }
    // wf1: 6->32, 224->112; P=115, RM=2
    dconv_k<3,3,115,2><<<dim3(98, 1, BATCH), 256>>>(
        fftin, wf1, bf1, hf1, 6, 224, 224, 12544, 0, 0, (long long)BATCH * HW, (long long)HW);
    // wf2: 32->64, 112->56; P=59, RM=4
    dconv_k<3,3,59,4><<<dim3(25, 1, BATCH), 256>>>(
        hf1, wf2, bf2, hf2, 32, 112, 112, 3136, 0, 0, 64LL * 12544, 12544LL);
    pool7_k<<<(64 * BATCH * 49 + 255) / 256, 256>>>(hf2, pooled, 3136);

    // ---- fusion + classifier ----
    run_sgemm(pooled, W_freq, comb + 512, 64, 512, 6272, b_freq, 1, 1.f, 0.f, 1024);
    run_sgemm(comb, W_fu1, buf1, 64, 1024, 1024, b_fu1, 1);
    run_sgemm(buf1, W_fu2, fused, 64, 512, 1024, b_fu2, 1);
    cls_k<<<1, 128>>>(fused, W_cls, b_cls, temp, out);
}

// round 4
// speedup vs baseline: 1.3155x; 1.0888x over previous
#include <cuda_runtime.h>
#include <cuda_bf16.h>
#include <math.h>

#define BATCH 64
#define IMG 224
#define HW  (IMG*IMG)          // 50176

__device__ float g_h0[64LL*64*112*112];
__device__ float g_h1[128LL*64*56*56];
__device__ float g_h2[256LL*64*28*28];
__device__ float g_h3[512LL*64*14*14];
__device__ float g_hd1[32LL*64*112*112];
__device__ float g_hd2[64LL*64*56*56];
__device__ float g_hf1[32LL*64*112*112];
__device__ float g_hf2[64LL*64*56*56];
__device__ float g_dctimg[BATCH*64];
__device__ float g_dctres[BATCH*HW];
__device__ float g_wd1s[32*9];
__device__ float g_Wre[HW];
__device__ float g_Wim[HW];
__device__ float g_D8[64];
__device__ float g_Zre[43008LL*128];     // stage-1 out (128 freq cols)
__device__ float g_Zim[43008LL*128];
__device__ float g_Ztre[24576LL*224];    // [192][128][224]
__device__ float g_Ztim[24576LL*224];
__device__ float g_Gre[24576LL*224];     // compact G (rows k=0..127 per image)
__device__ float g_Gim[24576LL*224];
__device__ float g_fftin[6LL*BATCH*HW];
__device__ float g_pooled[BATCH*6272];
__device__ float g_comb[BATCH*1024];
__device__ float g_buf1[BATCH*1024];
__device__ float g_fused[BATCH*512];

// ---------------------------------------------------------------------------
// Direct stride-2 conv, parity-split smem staging. RM=8 rows/thread fixed.
// Template: KH,KW, P (even/odd row pitch = OW + KW/2 + 2), TM (Co tile).
// Threads = 2*TM. Grid: (ceil(OH*OW/128), Co/TM, BATCH).
// ---------------------------------------------------------------------------
template<int KH, int KW, int P, int TM>
__global__ void __launch_bounds__(2*TM) dconv_k(
    const float* __restrict__ src, const float* __restrict__ Wt,
    const float* __restrict__ bias, float* __restrict__ dst,
    int Ci, int H, int W, int OHOW, int padh, int padw,
    long long sC, long long sB)
{
    constexpr int NT = 2 * TM;
    constexpr int OW = P - (KW / 2) - 2;
    constexpr int NR = 126 / OW + 2;
    constexpr int R  = 2 * (NR - 1) + KH;
    constexpr int KK = KH * KW;

    __shared__ float As[KK * TM];
    __shared__ float Sb[2 * R * P];

    int tid = threadIdx.x;
    int tx = tid & 15, ty = tid >> 4;          // ty in [0, TM/8)
    int row0 = blockIdx.y * TM;
    int bz = blockIdx.z;
    int s0 = blockIdx.x * 128;
    int oh_lo = s0 / OW;
    int base_ih = 2 * oh_lo - padh;
    const float* sp = src + bz * sB;

    int pbase[8];
    unsigned okmask = 0;
#pragma unroll
    for (int j = 0; j < 8; j++) {
        int s = s0 + j * 16 + tx;
        if (s < OHOW) okmask |= (1u << j);
        int sc = (s < OHOW) ? s : (OHOW - 1);
        int oh = sc / OW;
        int ow = sc - oh * OW;
        pbase[j] = 2 * (oh - oh_lo) * P + ow;
    }

    float acc[8][8];
#pragma unroll
    for (int i = 0; i < 8; i++)
#pragma unroll
        for (int j = 0; j < 8; j++) acc[i][j] = 0.f;

    for (int c = 0; c < Ci; c++) {
        for (int t = tid; t < KK * TM; t += NT) {
            int m = t / KK, tap = t - m * KK;
            As[tap * TM + m] = Wt[(long long)(row0 + m) * (Ci * KK) + c * KK + tap];
        }
        {
            const float* cp = sp + c * sC;
            for (int t = tid; t < R * 2 * P; t += NT) {
                int r = t / (2 * P);
                int u = t - r * 2 * P;
                int ih = base_ih + r;
                int ic = u - padw;
                float v = 0.f;
                if ((unsigned)ih < (unsigned)H && (unsigned)ic < (unsigned)W)
                    v = cp[(long long)ih * W + ic];
                Sb[(u & 1) * (R * P) + r * P + (u >> 1)] = v;
            }
        }
        __syncthreads();

#pragma unroll
        for (int kh = 0; kh < KH; kh++) {
#pragma unroll
            for (int kw = 0; kw < KW; kw++) {
                const float* bb = Sb + (kw & 1) * (R * P) + kh * P + (kw >> 1);
                float a[8];
                *(float4*)&a[0] = *(const float4*)&As[(kh * KW + kw) * TM + ty * 8];
                *(float4*)&a[4] = *(const float4*)&As[(kh * KW + kw) * TM + ty * 8 + 4];
#pragma unroll
                for (int j = 0; j < 8; j++) {
                    float bv = bb[pbase[j]];
#pragma unroll
                    for (int i = 0; i < 8; i++) acc[i][j] += a[i] * bv;
                }
            }
        }
        __syncthreads();
    }

    long long NtotG = (long long)BATCH * OHOW;
#pragma unroll
    for (int i = 0; i < 8; i++) {
        int gm = row0 + ty * 8 + i;
        float bm = bias[gm];
        float* drow = dst + (long long)gm * NtotG + (long long)bz * OHOW;
#pragma unroll
        for (int j = 0; j < 8; j++) {
            if (okmask & (1u << j)) {
                int s = s0 + j * 16 + tx;
                drow[s] = fmaxf(acc[i][j] + bm, 0.f);
            }
        }
    }
}

// ---------------------------------------------------------------------------
// Dense SGEMM: C = alpha*A*B + beta*C + biasN (+relu); ldb for strided B.
// ---------------------------------------------------------------------------
__global__ void __launch_bounds__(256) sgemm_k(
    const float* __restrict__ A, const float* __restrict__ B, float* __restrict__ C,
    int M, int N, int K, int ldc, int ldb, float alpha, float beta,
    const float* __restrict__ biasN, int relu)
{
    __shared__ float As[8][128];
    __shared__ float Bs[8][128];
    int tid = threadIdx.x;
    int tx = tid & 15, ty = tid >> 4;
    int row0 = blockIdx.y * 128, col0 = blockIdx.x * 128;

    float acc[8][8];
#pragma unroll
    for (int i = 0; i < 8; i++)
#pragma unroll
        for (int j = 0; j < 8; j++) acc[i][j] = 0.f;

    for (int k0 = 0; k0 < K; k0 += 8) {
#pragma unroll
        for (int i = 0; i < 4; i++) {
            int idx = tid + i * 256;
            int m = idx >> 3, kk = idx & 7;
            int gm = row0 + m, gk = k0 + kk;
            float v = 0.f;
            if (gm < M && gk < K) v = A[(long long)gm * K + gk];
            As[kk][m] = v;
        }
#pragma unroll
        for (int i = 0; i < 4; i++) {
            int idx = tid + i * 256;
            int kk = idx >> 7, nn = idx & 127;
            int gn = col0 + nn, gk = k0 + kk;
            float v = 0.f;
            if (gk < K && gn < N) v = B[(long long)gk * ldb + gn];
            Bs[kk][nn] = v;
        }
        __syncthreads();
#pragma unroll
        for (int kk = 0; kk < 8; kk++) {
            float a[8], b[8];
            *(float4*)&a[0] = *(const float4*)&As[kk][ty * 8];
            *(float4*)&a[4] = *(const float4*)&As[kk][ty * 8 + 4];
            *(float4*)&b[0] = *(const float4*)&Bs[kk][tx * 8];
            *(float4*)&b[4] = *(const float4*)&Bs[kk][tx * 8 + 4];
#pragma unroll
            for (int i = 0; i < 8; i++)
#pragma unroll
                for (int j = 0; j < 8; j++) acc[i][j] += a[i] * b[j];
        }
        __syncthreads();
    }

#pragma unroll
    for (int i = 0; i < 8; i++) {
        int gm = row0 + ty * 8 + i;
        if (gm >= M) continue;
#pragma unroll
        for (int j = 0; j < 8; j++) {
            int gn = col0 + tx * 8 + j;
            if (gn >= N) continue;
            float v = alpha * acc[i][j];
            if (beta != 0.f) v += beta * C[(long long)gm * ldc + gn];
            if (biasN) v += biasN[gn];
            if (relu) v = fmaxf(v, 0.f);
            C[(long long)gm * ldc + gn] = v;
        }
    }
}

// ---------------------------------------------------------------------------
// Fused complex GEMM (DFT stage 2): for A=(Are,Aim) [24576,224],
// B=(Bre,Bim) [224,224]: Cre = Are*Bre - Aim*Bim; Cim = Are*Bim + Aim*Bre.
// TM=64, TN=128, micro 4x8.
// ---------------------------------------------------------------------------
__global__ void __launch_bounds__(256) dft2_k(
    const float* __restrict__ Are, const float* __restrict__ Aim,
    const float* __restrict__ Bre, const float* __restrict__ Bim,
    float* __restrict__ Cre, float* __restrict__ Cim)
{
    __shared__ float As1[8][64], As2[8][64];
    __shared__ float Bs1[8][128], Bs2[8][128];
    int tid = threadIdx.x;
    int tx = tid & 15, ty = tid >> 4;
    int row0 = blockIdx.y * 64, col0 = blockIdx.x * 128;

    float are[4][8], aim[4][8];
#pragma unroll
    for (int i = 0; i < 4; i++)
#pragma unroll
        for (int j = 0; j < 8; j++) { are[i][j] = 0.f; aim[i][j] = 0.f; }

    for (int k0 = 0; k0 < 224; k0 += 8) {
#pragma unroll
        for (int i = 0; i < 2; i++) {
            int idx = tid + i * 256;
            int m = idx >> 3, kk = idx & 7;
            As1[kk][m] = Are[(long long)(row0 + m) * 224 + k0 + kk];
            As2[kk][m] = Aim[(long long)(row0 + m) * 224 + k0 + kk];
        }
#pragma unroll
        for (int i = 0; i < 4; i++) {
            int idx = tid + i * 256;
            int kk = idx >> 7, nn = idx & 127;
            int gn = col0 + nn;
            float v1 = 0.f, v2 = 0.f;
            if (gn < 224) {
                v1 = Bre[(k0 + kk) * 224 + gn];
                v2 = Bim[(k0 + kk) * 224 + gn];
            }
            Bs1[kk][nn] = v1;
            Bs2[kk][nn] = v2;
        }
        __syncthreads();
#pragma unroll
        for (int kk = 0; kk < 8; kk++) {
            float a1[4], a2[4], b1[8], b2[8];
            *(float4*)&a1[0] = *(const float4*)&As1[kk][ty * 4];
            *(float4*)&a2[0] = *(const float4*)&As2[kk][ty * 4];
            *(float4*)&b1[0] = *(const float4*)&Bs1[kk][tx * 8];
            *(float4*)&b1[4] = *(const float4*)&Bs1[kk][tx * 8 + 4];
            *(float4*)&b2[0] = *(const float4*)&Bs2[kk][tx * 8];
            *(float4*)&b2[4] = *(const float4*)&Bs2[kk][tx * 8 + 4];
#pragma unroll
            for (int i = 0; i < 4; i++)
#pragma unroll
                for (int j = 0; j < 8; j++) {
                    are[i][j] += a1[i] * b1[j];
                    are[i][j] -= a2[i] * b2[j];
                    aim[i][j] += a1[i] * b2[j];
                    aim[i][j] += a2[i] * b1[j];
                }
        }
        __syncthreads();
    }

#pragma unroll
    for (int i = 0; i < 4; i++) {
        long long gm = row0 + ty * 4 + i;
#pragma unroll
        for (int j = 0; j < 8; j++) {
            int gn = col0 + tx * 8 + j;
            if (gn < 224) {
                Cre[gm * 224 + gn] = are[i][j];
                Cim[gm * 224 + gn] = aim[i][j];
            }
        }
    }
}

// ---------------------------------------------------------------------------
// Small kernels
// ---------------------------------------------------------------------------
__global__ void genW_k(float* Wre, float* Wim) {
    int gid = blockIdx.x * blockDim.x + threadIdx.x;
    if (gid >= HW) return;
    int j = gid / IMG, k = gid % IMG;
    int r = (j * k) % IMG;
    float a = 2.f * (float)r / (float)IMG;
    Wre[gid] = cospif(a);
    Wim[gid] = -sinpif(a);
}

__global__ void genD8_k(float* D) {
    int tid = threadIdx.x;
    if (tid >= 64) return;
    int i = tid >> 3, j = tid & 7;
    float v = 0.5f * cospif((float)((2 * j + 1) * i) / 16.f);
    if (i == 0) v *= 0.7071067811865476f;
    D[tid] = v;
}

__global__ void wsum_k(const float* __restrict__ wd1, float* __restrict__ wd1s) {
    int tid = blockIdx.x * blockDim.x + threadIdx.x;
    if (tid >= 288) return;
    int o = tid / 9, r = tid % 9;
    wd1s[tid] = wd1[(o * 3 + 0) * 9 + r] + wd1[(o * 3 + 1) * 9 + r] + wd1[(o * 3 + 2) * 9 + r];
}

__global__ void dct_mean_k(const float* __restrict__ x, const float* __restrict__ D,
                           float* __restrict__ dctimg)
{
    __shared__ float part[8][64];
    __shared__ float Mb[64];
    __shared__ float T[64];
    int b = blockIdx.x;
    int tid = threadIdx.x;            // 512
    int ij = tid & 63, ch = tid >> 6;
    int i = ij >> 3, j = ij & 7;
    const float* xb = x + (long long)b * 3 * HW;
    float s = 0.f;
    for (int blk = ch; blk < 784; blk += 8) {
        int m = blk / 28, n = blk % 28;
        int idx = (m * 8 + i) * IMG + (n * 8 + j);
        s += 0.299f * xb[idx] + 0.587f * xb[idx + HW] + 0.114f * xb[idx + 2 * HW];
    }
    part[ch][ij] = s;
    __syncthreads();
    if (tid < 64) {
        float t = 0.f;
        for (int c = 0; c < 8; c++) t += part[c][tid];
        Mb[tid] = t * (255.f / 784.f);
    }
    __syncthreads();
    if (tid < 64) {
        float t = 0.f;
        for (int k = 0; k < 8; k++) t += D[i * 8 + k] * Mb[k * 8 + j];
        T[tid] = t;
    }
    __syncthreads();
    if (tid < 64) {
        float o = 0.f;
        for (int k = 0; k < 8; k++) o += T[i * 8 + k] * D[j * 8 + k];
        dctimg[b * 64 + tid] = o;
    }
}

__global__ void resize_k(const float* __restrict__ dctimg, float* __restrict__ out) {
    int gid = blockIdx.x * blockDim.x + threadIdx.x;
    if (gid >= BATCH * HW) return;
    int ow = gid % IMG;
    int t = gid / IMG;
    int oh = t % IMG;
    int b = t / IMG;
    float fh = (oh + 0.5f) * (8.f / 224.f) - 0.5f;
    float fw = (ow + 0.5f) * (8.f / 224.f) - 0.5f;
    fh = fminf(fmaxf(fh, 0.f), 7.f);
    fw = fminf(fmaxf(fw, 0.f), 7.f);
    int h0 = (int)floorf(fh), w0 = (int)floorf(fw);
    int h1 = min(h0 + 1, 7), w1 = min(w0 + 1, 7);
    float ah = fh - (float)h0, aw = fw - (float)w0;
    const float* d = dctimg + b * 64;
    float v00 = d[h0 * 8 + w0], v01 = d[h0 * 8 + w1];
    float v10 = d[h1 * 8 + w0], v11 = d[h1 * 8 + w1];
    out[gid] = (1.f - ah) * ((1.f - aw) * v00 + aw * v01) + ah * ((1.f - aw) * v10 + aw * v11);
}

// transpose Z [192*224 x 128ld] -> Zt [192][128][224]
__global__ void transpose_z_k(const float* __restrict__ src, float* __restrict__ dst) {
    __shared__ float tile[32][33];
    int m = blockIdx.z;
    int i0 = blockIdx.x * 32;   // i in [0,224)
    int k0 = blockIdx.y * 32;   // k in [0,128)
    int tx = threadIdx.x, ty = threadIdx.y;
    tile[ty][tx] = src[((long long)m * 224 + i0 + ty) * 128 + k0 + tx];
    __syncthreads();
    dst[((long long)m * 128 + k0 + ty) * 224 + i0 + tx] = tile[tx][ty];
}

// fftin[(2c+p)][b][h][w] = G[m=b*3+c][w][h] with Hermitian mirror for w>=113:
// G[w][h] = sgn * Gc[224-w][(224-h)%224]  (sgn=-1 for imag part)
__global__ void fftin2_k(const float* __restrict__ Gc, float* __restrict__ fftin,
                         int p, float sgn) {
    __shared__ float tile[32][33];
    int m = blockIdx.z;
    int b = m / 3, c = m % 3;
    int i0 = blockIdx.y * 32;   // w rows
    int j0 = blockIdx.x * 32;   // h cols
    int tx = threadIdx.x, ty = threadIdx.y;
    int w = i0 + ty, h = j0 + tx;
    float v;
    if (w < 113) {
        v = Gc[((long long)m * 128 + w) * 224 + h];
    } else {
        int hs = (224 - h) % 224;
        v = sgn * Gc[((long long)m * 128 + (224 - w)) * 224 + hs];
    }
    tile[ty][tx] = v;
    __syncthreads();
    fftin[((long long)(2 * c + p) * BATCH + b) * HW + (j0 + ty) * 224 + (i0 + tx)] = tile[tx][ty];
}

__global__ void pool7_k(const float* __restrict__ src, float* __restrict__ pooled, int base) {
    int gid = blockIdx.x * blockDim.x + threadIdx.x;
    if (gid >= 64 * BATCH * 49) return;
    int j = gid % 7;
    int t = gid / 7;
    int i = t % 7;
    t /= 7;
    int c = t % 64;
    int b = t / 64;
    const float* s = src + ((long long)c * BATCH + b) * 56 * 56;
    float acc = 0.f;
#pragma unroll
    for (int p = 0; p < 8; p++)
#pragma unroll
        for (int q = 0; q < 8; q++)
            acc += s[(i * 8 + p) * 56 + (j * 8 + q)];
    pooled[b * 6272 + base + c * 49 + i * 7 + j] = acc * (1.f / 64.f);
}

__global__ void gap_k(const float* __restrict__ h3, float* __restrict__ comb) {
    int gid = blockIdx.x * blockDim.x + threadIdx.x;
    if (gid >= 512 * BATCH) return;
    int c = gid / BATCH, b = gid % BATCH;
    const float* s = h3 + ((long long)c * BATCH + b) * 196;
    float acc = 0.f;
    for (int t = 0; t < 196; t++) acc += s[t];
    comb[b * 1024 + c] = acc * (1.f / 196.f);
}

__global__ void cls_k(const float* __restrict__ fused, const float* __restrict__ Wc,
                      const float* __restrict__ bc, const float* __restrict__ temp,
                      float* __restrict__ out)
{
    int tid = threadIdx.x; // 128
    if (tid >= 128) return;
    int b = tid >> 1, j = tid & 1;
    float s = bc[j];
    const float* f = fused + b * 512;
    for (int k = 0; k < 512; k++) s += f[k] * Wc[k * 2 + j];
    out[b * 2 + j] = s;
    out[128 + b * 2 + j] = s / temp[0];
}

// ---------------------------------------------------------------------------
static void run_sgemm(const float* A, const float* B, float* C, int M, int N, int K,
                      const float* biasN, int relu,
                      float alpha = 1.f, float beta = 0.f, int ldc = -1, int ldb = -1)
{
    if (ldc < 0) ldc = N;
    if (ldb < 0) ldb = N;
    dim3 grid((N + 127) / 128, (M + 127) / 128);
    sgemm_k<<<grid, 256>>>(A, B, C, M, N, K, ldc, ldb, alpha, beta, biasN, relu);
}

extern "C" void kernel_launch(void* const* d_in, const int* in_sizes, int n_in,
                              void* d_out, int out_size)
{
    const float* x      = (const float*)d_in[0];
    const float* w_stem = (const float*)d_in[1];
    const float* b_stem = (const float*)d_in[2];
    const float* w1     = (const float*)d_in[3];
    const float* b1     = (const float*)d_in[4];
    const float* w2     = (const float*)d_in[5];
    const float* b2     = (const float*)d_in[6];
    const float* w3     = (const float*)d_in[7];
    const float* b3     = (const float*)d_in[8];
    const float* wd1    = (const float*)d_in[9];
    const float* bd1    = (const float*)d_in[10];
    const float* wd2    = (const float*)d_in[11];
    const float* bd2    = (const float*)d_in[12];
    const float* wf1    = (const float*)d_in[13];
    const float* bf1    = (const float*)d_in[14];
    const float* wf2    = (const float*)d_in[15];
    const float* bf2    = (const float*)d_in[16];
    const float* W_freq = (const float*)d_in[17];
    const float* b_freq = (const float*)d_in[18];
    const float* W_fu1  = (const float*)d_in[19];
    const float* b_fu1  = (const float*)d_in[20];
    const float* W_fu2  = (const float*)d_in[21];
    const float* b_fu2  = (const float*)d_in[22];
    const float* W_cls  = (const float*)d_in[23];
    const float* b_cls  = (const float*)d_in[24];
    const float* temp   = (const float*)d_in[25];
    float* out = (float*)d_out;

    float *h0, *h1, *h2, *h3, *hd1, *hd2, *hf1, *hf2;
    float *dctimg, *dctres, *wd1s, *Wre, *Wim, *D8;
    float *Zre, *Zim, *Ztre, *Ztim, *Gre, *Gim, *fftin;
    float *pooled, *comb, *buf1, *fused;
    cudaGetSymbolAddress((void**)&h0, g_h0);
    cudaGetSymbolAddress((void**)&h1, g_h1);
    cudaGetSymbolAddress((void**)&h2, g_h2);
    cudaGetSymbolAddress((void**)&h3, g_h3);
    cudaGetSymbolAddress((void**)&hd1, g_hd1);
    cudaGetSymbolAddress((void**)&hd2, g_hd2);
    cudaGetSymbolAddress((void**)&hf1, g_hf1);
    cudaGetSymbolAddress((void**)&hf2, g_hf2);
    cudaGetSymbolAddress((void**)&dctimg, g_dctimg);
    cudaGetSymbolAddress((void**)&dctres, g_dctres);
    cudaGetSymbolAddress((void**)&wd1s, g_wd1s);
    cudaGetSymbolAddress((void**)&Wre, g_Wre);
    cudaGetSymbolAddress((void**)&Wim, g_Wim);
    cudaGetSymbolAddress((void**)&D8, g_D8);
    cudaGetSymbolAddress((void**)&Zre, g_Zre);
    cudaGetSymbolAddress((void**)&Zim, g_Zim);
    cudaGetSymbolAddress((void**)&Ztre, g_Ztre);
    cudaGetSymbolAddress((void**)&Ztim, g_Ztim);
    cudaGetSymbolAddress((void**)&Gre, g_Gre);
    cudaGetSymbolAddress((void**)&Gim, g_Gim);
    cudaGetSymbolAddress((void**)&fftin, g_fftin);
    cudaGetSymbolAddress((void**)&pooled, g_pooled);
    cudaGetSymbolAddress((void**)&comb, g_comb);
    cudaGetSymbolAddress((void**)&buf1, g_buf1);
    cudaGetSymbolAddress((void**)&fused, g_fused);

    // ---- init constants ----
    genW_k<<<(HW + 255) / 256, 256>>>(Wre, Wim);
    genD8_k<<<1, 64>>>(D8);
    wsum_k<<<2, 256>>>(wd1, wd1s);

    // ---- CNN backbone ----
    // stem: 3->64, 7x7 s2, pad 2; TM=64 (128 threads)
    dconv_k<7,7,117,64><<<dim3(98, 1, BATCH), 128>>>(
        x, w_stem, b_stem, h0, 3, 224, 224, 12544, 2, 2, (long long)HW, 3LL * HW);
    // conv1: 64->128, 112->56
    dconv_k<3,3,59,128><<<dim3(25, 1, BATCH), 256>>>(
        h0, w1, b1, h1, 64, 112, 112, 3136, 0, 0, 64LL * 12544, 12544LL);
    // conv2: 128->256, 56->28
    dconv_k<3,3,31,128><<<dim3(7, 2, BATCH), 256>>>(
        h1, w2, b2, h2, 128, 56, 56, 784, 0, 0, 64LL * 3136, 3136LL);
    // conv3: 256->512, 28->14
    dconv_k<3,3,17,128><<<dim3(2, 4, BATCH), 256>>>(
        h2, w3, b3, h3, 256, 28, 28, 196, 0, 0, 64LL * 784, 784LL);
    gap_k<<<(512 * BATCH + 255) / 256, 256>>>(h3, comb);

    // ---- DCT branch ----
    dct_mean_k<<<BATCH, 512>>>(x, D8, dctimg);
    resize_k<<<(BATCH * HW + 255) / 256, 256>>>(dctimg, dctres);
    // wd1 (folded, Ci=1): 1->32; TM=32 (64 threads)
    dconv_k<3,3,115,32><<<dim3(98, 1, BATCH), 64>>>(
        dctres, wd1s, bd1, hd1, 1, 224, 224, 12544, 0, 0, 0LL, (long long)HW);
    // wd2: 32->64; TM=64 (128 threads)
    dconv_k<3,3,59,64><<<dim3(25, 1, BATCH), 128>>>(
        hd1, wd2, bd2, hd2, 32, 112, 112, 3136, 0, 0, 64LL * 12544, 12544LL);
    pool7_k<<<(64 * BATCH * 49 + 255) / 256, 256>>>(hd2, pooled, 0);

    // ---- FFT branch (Hermitian-reduced DFT) ----
    // stage 1: Z = X * W, only 128 frequency columns (cols 0..112 used + extra)
    run_sgemm(x, Wre, Zre, 43008, 128, 224, nullptr, 0, 1.f, 0.f, 128, 224);
    run_sgemm(x, Wim, Zim, 43008, 128, 224, nullptr, 0, 1.f, 0.f, 128, 224);
    {
        dim3 tgrid(7, 4, 192), tblk(32, 32);
        transpose_z_k<<<tgrid, tblk>>>(Zre, Ztre);
        transpose_z_k<<<tgrid, tblk>>>(Zim, Ztim);
    }
    // stage 2: fused complex GEMM over compact rows (M = 192*128)
    dft2_k<<<dim3(2, 384), 256>>>(Ztre, Ztim, Wre, Wim, Gre, Gim);
    {
        dim3 tgrid(7, 7, 192), tblk(32, 32);
        fftin2_k<<<tgrid, tblk>>>(Gre, fftin, 0,  1.f);
        fftin2_k<<<tgrid, tblk>>>(Gim, fftin, 1, -1.f);
    }
    // wf1: 6->32; TM=32
    dconv_k<3,3,115,32><<<dim3(98, 1, BATCH), 64>>>(
        fftin, wf1, bf1, hf1, 6, 224, 224, 12544, 0, 0, (long long)BATCH * HW, (long long)HW);
    // wf2: 32->64; TM=64
    dconv_k<3,3,59,64><<<dim3(25, 1, BATCH), 128>>>(
        hf1, wf2, bf2, hf2, 32, 112, 112, 3136, 0, 0, 64LL * 12544, 12544LL);
    pool7_k<<<(64 * BATCH * 49 + 255) / 256, 256>>>(hf2, pooled, 3136);

    // ---- fusion + classifier ----
    run_sgemm(pooled, W_freq, comb + 512, 64, 512, 6272, b_freq, 1, 1.f, 0.f, 1024);
    run_sgemm(comb, W_fu1, buf1, 64, 1024, 1024, b_fu1, 1);
    run_sgemm(buf1, W_fu2, fused, 64, 512, 1024, b_fu2, 1);
    cls_k<<<1, 128>>>(fused, W_cls, b_cls, temp, out);
}

// round 5
// speedup vs baseline: 1.6558x; 1.2587x over previous
#include <cuda_runtime.h>
#include <cuda_bf16.h>
#include <math.h>

#define BATCH 64
#define IMG 224
#define HW  (IMG*IMG)          // 50176

__device__ float g_h0[64LL*64*112*112];
__device__ float g_h1[128LL*64*56*56];
__device__ float g_h2[256LL*64*28*28];
__device__ float g_h3[512LL*64*14*14];
__device__ float g_hd1[32LL*64*112*112];
__device__ float g_hd2[64LL*64*56*56];
__device__ float g_hf1[32LL*64*112*112];
__device__ float g_hf2[64LL*64*56*56];
__device__ float g_dctimg[BATCH*64];
__device__ float g_dctres[BATCH*HW];
__device__ float g_wd1s[32*9];
__device__ float g_Wre[HW];
__device__ float g_Wim[HW];
__device__ float g_D8[64];
__device__ float g_Zre[43008LL*128];
__device__ float g_Zim[43008LL*128];
__device__ float g_Ztre[24576LL*224];
__device__ float g_Ztim[24576LL*224];
__device__ float g_Gre[24576LL*224];
__device__ float g_Gim[24576LL*224];
__device__ float g_fftin[6LL*BATCH*HW];
__device__ float g_pooled[BATCH*6272];
__device__ float g_comb[BATCH*1024];
__device__ float g_buf1[BATCH*1024];
__device__ float g_fused[BATCH*512];

// ---- packed f32x2 helpers -------------------------------------------------
__device__ __forceinline__ unsigned long long ffma2(
    unsigned long long a, unsigned long long b, unsigned long long c)
{
    unsigned long long d;
    asm("fma.rn.f32x2 %0, %1, %2, %3;" : "=l"(d) : "l"(a), "l"(b), "l"(c));
    return d;
}
__device__ __forceinline__ unsigned long long dup2(float v) {
    unsigned long long r;
    asm("mov.b64 %0, {%1, %1};" : "=l"(r) : "f"(v));
    return r;
}
__device__ __forceinline__ float2 unpk2(unsigned long long v) {
    float2 f;
    asm("mov.b64 {%0, %1}, %2;" : "=f"(f.x), "=f"(f.y) : "l"(v));
    return f;
}

// ---------------------------------------------------------------------------
// Direct stride-2 conv, parity-split smem staging, FFMA2 accumulation.
// KH,KW taps; P = OW + KW/2 + 2; TM = Co tile (8 rows/thread); NC channels
// staged per sync. Threads = 2*TM. Grid: (ceil(OH*OW/128), Co/TM, BATCH).
// ---------------------------------------------------------------------------
template<int KH, int KW, int P, int TM, int NC>
__global__ void __launch_bounds__(2*TM) dconv_k(
    const float* __restrict__ src, const float* __restrict__ Wt,
    const float* __restrict__ bias, float* __restrict__ dst,
    int Ci, int H, int W, int OHOW, int padh, int padw,
    long long sC, long long sB)
{
    constexpr int NT = 2 * TM;
    constexpr int OW = P - (KW / 2) - 2;
    constexpr int NR = 126 / OW + 2;
    constexpr int R  = 2 * (NR - 1) + KH;
    constexpr int KK = KH * KW;
    constexpr int CP = 2 * R * P;          // floats per staged channel

    __shared__ __align__(16) float As[KK * TM * NC];
    __shared__ __align__(16) float Sb[CP * NC];

    int tid = threadIdx.x;
    int tx = tid & 15, ty = tid >> 4;
    int row0 = blockIdx.y * TM;
    int bz = blockIdx.z;
    int s0 = blockIdx.x * 128;
    int oh_lo = s0 / OW;
    int base_ih = 2 * oh_lo - padh;
    const float* sp = src + bz * sB;

    int pbase[8];
    unsigned okmask = 0;
#pragma unroll
    for (int j = 0; j < 8; j++) {
        int s = s0 + j * 16 + tx;
        if (s < OHOW) okmask |= (1u << j);
        int sc = (s < OHOW) ? s : (OHOW - 1);
        int oh = sc / OW;
        int ow = sc - oh * OW;
        pbase[j] = 2 * (oh - oh_lo) * P + ow;
    }

    unsigned long long acc2[4][8];
#pragma unroll
    for (int p = 0; p < 4; p++)
#pragma unroll
        for (int j = 0; j < 8; j++) acc2[p][j] = 0ULL;

    for (int c0 = 0; c0 < Ci; c0 += NC) {
        // stage weights for NC channels
        for (int t = tid; t < KK * TM * NC; t += NT) {
            int cc = t / (KK * TM);
            int rem = t - cc * (KK * TM);
            int m = rem / KK, tap = rem - m * KK;
            As[(cc * KK + tap) * TM + m] =
                Wt[(long long)(row0 + m) * (Ci * KK) + (c0 + cc) * KK + tap];
        }
        // stage inputs for NC channels (parity-split)
        for (int t = tid; t < CP * NC; t += NT) {
            int cc = t / CP;
            int rem = t - cc * CP;
            int r = rem / (2 * P);
            int u = rem - r * 2 * P;
            int ih = base_ih + r;
            int ic = u - padw;
            float v = 0.f;
            if ((unsigned)ih < (unsigned)H && (unsigned)ic < (unsigned)W)
                v = sp[(c0 + cc) * sC + (long long)ih * W + ic];
            Sb[cc * CP + (u & 1) * (R * P) + r * P + (u >> 1)] = v;
        }
        __syncthreads();

#pragma unroll
        for (int cc = 0; cc < NC; cc++) {
#pragma unroll
            for (int kh = 0; kh < KH; kh++) {
#pragma unroll
                for (int kw = 0; kw < KW; kw++) {
                    const float* aw = &As[(cc * KK + kh * KW + kw) * TM + ty * 8];
                    const float* bb = Sb + cc * CP + (kw & 1) * (R * P) + kh * P + (kw >> 1);
                    unsigned long long a2[4];
#pragma unroll
                    for (int p = 0; p < 4; p++)
                        a2[p] = *(const unsigned long long*)&aw[2 * p];
#pragma unroll
                    for (int j = 0; j < 8; j++) {
                        unsigned long long b2 = dup2(bb[pbase[j]]);
#pragma unroll
                        for (int p = 0; p < 4; p++)
                            acc2[p][j] = ffma2(a2[p], b2, acc2[p][j]);
                    }
                }
            }
        }
        __syncthreads();
    }

    long long NtotG = (long long)BATCH * OHOW;
#pragma unroll
    for (int p = 0; p < 4; p++) {
        int gm0 = row0 + ty * 8 + 2 * p;
        float bm0 = bias[gm0], bm1 = bias[gm0 + 1];
        float* d0 = dst + (long long)gm0 * NtotG + (long long)bz * OHOW;
        float* d1 = d0 + NtotG;
#pragma unroll
        for (int j = 0; j < 8; j++) {
            if (okmask & (1u << j)) {
                int s = s0 + j * 16 + tx;
                float2 v = unpk2(acc2[p][j]);
                d0[s] = fmaxf(v.x + bm0, 0.f);
                d1[s] = fmaxf(v.y + bm1, 0.f);
            }
        }
    }
}

// ---------------------------------------------------------------------------
// Dense SGEMM, FFMA2: C = alpha*A*B + beta*C + biasN (+relu)
// ---------------------------------------------------------------------------
__global__ void __launch_bounds__(256) sgemm_k(
    const float* __restrict__ A, const float* __restrict__ B, float* __restrict__ C,
    int M, int N, int K, int ldc, int ldb, float alpha, float beta,
    const float* __restrict__ biasN, int relu)
{
    __shared__ __align__(16) float As[8][128];
    __shared__ __align__(16) float Bs[8][128];
    int tid = threadIdx.x;
    int tx = tid & 15, ty = tid >> 4;
    int row0 = blockIdx.y * 128, col0 = blockIdx.x * 128;

    unsigned long long acc2[4][8];
#pragma unroll
    for (int p = 0; p < 4; p++)
#pragma unroll
        for (int j = 0; j < 8; j++) acc2[p][j] = 0ULL;

    for (int k0 = 0; k0 < K; k0 += 8) {
#pragma unroll
        for (int i = 0; i < 4; i++) {
            int idx = tid + i * 256;
            int m = idx >> 3, kk = idx & 7;
            int gm = row0 + m, gk = k0 + kk;
            float v = 0.f;
            if (gm < M && gk < K) v = A[(long long)gm * K + gk];
            As[kk][m] = v;
        }
#pragma unroll
        for (int i = 0; i < 4; i++) {
            int idx = tid + i * 256;
            int kk = idx >> 7, nn = idx & 127;
            int gn = col0 + nn, gk = k0 + kk;
            float v = 0.f;
            if (gk < K && gn < N) v = B[(long long)gk * ldb + gn];
            Bs[kk][nn] = v;
        }
        __syncthreads();
#pragma unroll
        for (int kk = 0; kk < 8; kk++) {
            unsigned long long a2[4];
#pragma unroll
            for (int p = 0; p < 4; p++)
                a2[p] = *(const unsigned long long*)&As[kk][ty * 8 + 2 * p];
            float b[8];
            *(float4*)&b[0] = *(const float4*)&Bs[kk][tx * 8];
            *(float4*)&b[4] = *(const float4*)&Bs[kk][tx * 8 + 4];
#pragma unroll
            for (int j = 0; j < 8; j++) {
                unsigned long long b2 = dup2(b[j]);
#pragma unroll
                for (int p = 0; p < 4; p++)
                    acc2[p][j] = ffma2(a2[p], b2, acc2[p][j]);
            }
        }
        __syncthreads();
    }

#pragma unroll
    for (int p = 0; p < 4; p++) {
        int gm0 = row0 + ty * 8 + 2 * p;
#pragma unroll
        for (int j = 0; j < 8; j++) {
            int gn = col0 + tx * 8 + j;
            if (gn >= N) continue;
            float2 v2 = unpk2(acc2[p][j]);
            float vv[2] = {v2.x, v2.y};
#pragma unroll
            for (int q = 0; q < 2; q++) {
                int gm = gm0 + q;
                if (gm >= M) continue;
                float v = alpha * vv[q];
                if (beta != 0.f) v += beta * C[(long long)gm * ldc + gn];
                if (biasN) v += biasN[gn];
                if (relu) v = fmaxf(v, 0.f);
                C[(long long)gm * ldc + gn] = v;
            }
        }
    }
}

// ---------------------------------------------------------------------------
// Fused complex GEMM (DFT stage 2), FFMA2.
// ---------------------------------------------------------------------------
__global__ void __launch_bounds__(256) dft2_k(
    const float* __restrict__ Are, const float* __restrict__ Aim,
    const float* __restrict__ Bre, const float* __restrict__ Bim,
    float* __restrict__ Cre, float* __restrict__ Cim)
{
    __shared__ __align__(16) float As1[8][64], As2[8][64];
    __shared__ __align__(16) float Bs1[8][128], Bs2[8][128];
    int tid = threadIdx.x;
    int tx = tid & 15, ty = tid >> 4;
    int row0 = blockIdx.y * 64, col0 = blockIdx.x * 128;

    unsigned long long are2[2][8], aim2[2][8];
#pragma unroll
    for (int p = 0; p < 2; p++)
#pragma unroll
        for (int j = 0; j < 8; j++) { are2[p][j] = 0ULL; aim2[p][j] = 0ULL; }

    for (int k0 = 0; k0 < 224; k0 += 8) {
#pragma unroll
        for (int i = 0; i < 2; i++) {
            int idx = tid + i * 256;
            int m = idx >> 3, kk = idx & 7;
            As1[kk][m] = Are[(long long)(row0 + m) * 224 + k0 + kk];
            As2[kk][m] = Aim[(long long)(row0 + m) * 224 + k0 + kk];
        }
#pragma unroll
        for (int i = 0; i < 4; i++) {
            int idx = tid + i * 256;
            int kk = idx >> 7, nn = idx & 127;
            int gn = col0 + nn;
            float v1 = 0.f, v2 = 0.f;
            if (gn < 224) {
                v1 = Bre[(k0 + kk) * 224 + gn];
                v2 = Bim[(k0 + kk) * 224 + gn];
            }
            Bs1[kk][nn] = v1;
            Bs2[kk][nn] = v2;
        }
        __syncthreads();
#pragma unroll
        for (int kk = 0; kk < 8; kk++) {
            unsigned long long a1p[2], a2p[2];
#pragma unroll
            for (int p = 0; p < 2; p++) {
                a1p[p] = *(const unsigned long long*)&As1[kk][ty * 4 + 2 * p];
                a2p[p] = *(const unsigned long long*)&As2[kk][ty * 4 + 2 * p];
            }
            float b1[8], b2[8];
            *(float4*)&b1[0] = *(const float4*)&Bs1[kk][tx * 8];
            *(float4*)&b1[4] = *(const float4*)&Bs1[kk][tx * 8 + 4];
            *(float4*)&b2[0] = *(const float4*)&Bs2[kk][tx * 8];
            *(float4*)&b2[4] = *(const float4*)&Bs2[kk][tx * 8 + 4];
#pragma unroll
            for (int j = 0; j < 8; j++) {
                unsigned long long db1 = dup2(b1[j]);
                unsigned long long db2 = dup2(b2[j]);
                unsigned long long dn2 = dup2(-b2[j]);
#pragma unroll
                for (int p = 0; p < 2; p++) {
                    are2[p][j] = ffma2(a1p[p], db1, are2[p][j]);
                    are2[p][j] = ffma2(a2p[p], dn2, are2[p][j]);
                    aim2[p][j] = ffma2(a1p[p], db2, aim2[p][j]);
                    aim2[p][j] = ffma2(a2p[p], db1, aim2[p][j]);
                }
            }
        }
        __syncthreads();
    }

#pragma unroll
    for (int p = 0; p < 2; p++) {
        long long gm0 = row0 + ty * 4 + 2 * p;
#pragma unroll
        for (int j = 0; j < 8; j++) {
            int gn = col0 + tx * 8 + j;
            if (gn < 224) {
                float2 vr = unpk2(are2[p][j]);
                float2 vi = unpk2(aim2[p][j]);
                Cre[gm0 * 224 + gn] = vr.x;
                Cre[(gm0 + 1) * 224 + gn] = vr.y;
                Cim[gm0 * 224 + gn] = vi.x;
                Cim[(gm0 + 1) * 224 + gn] = vi.y;
            }
        }
    }
}

// ---------------------------------------------------------------------------
// Small kernels
// ---------------------------------------------------------------------------
__global__ void genW_k(float* Wre, float* Wim) {
    int gid = blockIdx.x * blockDim.x + threadIdx.x;
    if (gid >= HW) return;
    int j = gid / IMG, k = gid % IMG;
    int r = (j * k) % IMG;
    float a = 2.f * (float)r / (float)IMG;
    Wre[gid] = cospif(a);
    Wim[gid] = -sinpif(a);
}

__global__ void genD8_k(float* D) {
    int tid = threadIdx.x;
    if (tid >= 64) return;
    int i = tid >> 3, j = tid & 7;
    float v = 0.5f * cospif((float)((2 * j + 1) * i) / 16.f);
    if (i == 0) v *= 0.7071067811865476f;
    D[tid] = v;
}

__global__ void wsum_k(const float* __restrict__ wd1, float* __restrict__ wd1s) {
    int tid = blockIdx.x * blockDim.x + threadIdx.x;
    if (tid >= 288) return;
    int o = tid / 9, r = tid % 9;
    wd1s[tid] = wd1[(o * 3 + 0) * 9 + r] + wd1[(o * 3 + 1) * 9 + r] + wd1[(o * 3 + 2) * 9 + r];
}

__global__ void dct_mean_k(const float* __restrict__ x, const float* __restrict__ D,
                           float* __restrict__ dctimg)
{
    __shared__ float part[8][64];
    __shared__ float Mb[64];
    __shared__ float T[64];
    int b = blockIdx.x;
    int tid = threadIdx.x;
    int ij = tid & 63, ch = tid >> 6;
    int i = ij >> 3, j = ij & 7;
    const float* xb = x + (long long)b * 3 * HW;
    float s = 0.f;
    for (int blk = ch; blk < 784; blk += 8) {
        int m = blk / 28, n = blk % 28;
        int idx = (m * 8 + i) * IMG + (n * 8 + j);
        s += 0.299f * xb[idx] + 0.587f * xb[idx + HW] + 0.114f * xb[idx + 2 * HW];
    }
    part[ch][ij] = s;
    __syncthreads();
    if (tid < 64) {
        float t = 0.f;
        for (int c = 0; c < 8; c++) t += part[c][tid];
        Mb[tid] = t * (255.f / 784.f);
    }
    __syncthreads();
    if (tid < 64) {
        float t = 0.f;
        for (int k = 0; k < 8; k++) t += D[i * 8 + k] * Mb[k * 8 + j];
        T[tid] = t;
    }
    __syncthreads();
    if (tid < 64) {
        float o = 0.f;
        for (int k = 0; k < 8; k++) o += T[i * 8 + k] * D[j * 8 + k];
        dctimg[b * 64 + tid] = o;
    }
}

__global__ void resize_k(const float* __restrict__ dctimg, float* __restrict__ out) {
    int gid = blockIdx.x * blockDim.x + threadIdx.x;
    if (gid >= BATCH * HW) return;
    int ow = gid % IMG;
    int t = gid / IMG;
    int oh = t % IMG;
    int b = t / IMG;
    float fh = (oh + 0.5f) * (8.f / 224.f) - 0.5f;
    float fw = (ow + 0.5f) * (8.f / 224.f) - 0.5f;
    fh = fminf(fmaxf(fh, 0.f), 7.f);
    fw = fminf(fmaxf(fw, 0.f), 7.f);
    int h0 = (int)floorf(fh), w0 = (int)floorf(fw);
    int h1 = min(h0 + 1, 7), w1 = min(w0 + 1, 7);
    float ah = fh - (float)h0, aw = fw - (float)w0;
    const float* d = dctimg + b * 64;
    float v00 = d[h0 * 8 + w0], v01 = d[h0 * 8 + w1];
    float v10 = d[h1 * 8 + w0], v11 = d[h1 * 8 + w1];
    out[gid] = (1.f - ah) * ((1.f - aw) * v00 + aw * v01) + ah * ((1.f - aw) * v10 + aw * v11);
}

__global__ void transpose_z_k(const float* __restrict__ src, float* __restrict__ dst) {
    __shared__ float tile[32][33];
    int m = blockIdx.z;
    int i0 = blockIdx.x * 32;
    int k0 = blockIdx.y * 32;
    int tx = threadIdx.x, ty = threadIdx.y;
    tile[ty][tx] = src[((long long)m * 224 + i0 + ty) * 128 + k0 + tx];
    __syncthreads();
    dst[((long long)m * 128 + k0 + ty) * 224 + i0 + tx] = tile[tx][ty];
}

__global__ void fftin2_k(const float* __restrict__ Gc, float* __restrict__ fftin,
                         int p, float sgn) {
    __shared__ float tile[32][33];
    int m = blockIdx.z;
    int b = m / 3, c = m % 3;
    int i0 = blockIdx.y * 32;
    int j0 = blockIdx.x * 32;
    int tx = threadIdx.x, ty = threadIdx.y;
    int w = i0 + ty, h = j0 + tx;
    float v;
    if (w < 113) {
        v = Gc[((long long)m * 128 + w) * 224 + h];
    } else {
        int hs = (224 - h) % 224;
        v = sgn * Gc[((long long)m * 128 + (224 - w)) * 224 + hs];
    }
    tile[ty][tx] = v;
    __syncthreads();
    fftin[((long long)(2 * c + p) * BATCH + b) * HW + (j0 + ty) * 224 + (i0 + tx)] = tile[tx][ty];
}

__global__ void pool7_k(const float* __restrict__ src, float* __restrict__ pooled, int base) {
    int gid = blockIdx.x * blockDim.x + threadIdx.x;
    if (gid >= 64 * BATCH * 49) return;
    int j = gid % 7;
    int t = gid / 7;
    int i = t % 7;
    t /= 7;
    int c = t % 64;
    int b = t / 64;
    const float* s = src + ((long long)c * BATCH + b) * 56 * 56;
    float acc = 0.f;
#pragma unroll
    for (int p = 0; p < 8; p++)
#pragma unroll
        for (int q = 0; q < 8; q++)
            acc += s[(i * 8 + p) * 56 + (j * 8 + q)];
    pooled[b * 6272 + base + c * 49 + i * 7 + j] = acc * (1.f / 64.f);
}

__global__ void gap_k(const float* __restrict__ h3, float* __restrict__ comb) {
    int gid = blockIdx.x * blockDim.x + threadIdx.x;
    if (gid >= 512 * BATCH) return;
    int c = gid / BATCH, b = gid % BATCH;
    const float* s = h3 + ((long long)c * BATCH + b) * 196;
    float acc = 0.f;
    for (int t = 0; t < 196; t++) acc += s[t];
    comb[b * 1024 + c] = acc * (1.f / 196.f);
}

__global__ void cls_k(const float* __restrict__ fused, const float* __restrict__ Wc,
                      const float* __restrict__ bc, const float* __restrict__ temp,
                      float* __restrict__ out)
{
    int tid = threadIdx.x;
    if (tid >= 128) return;
    int b = tid >> 1, j = tid & 1;
    float s = bc[j];
    const float* f = fused + b * 512;
    for (int k = 0; k < 512; k++) s += f[k] * Wc[k * 2 + j];
    out[b * 2 + j] = s;
    out[128 + b * 2 + j] = s / temp[0];
}

// ---------------------------------------------------------------------------
static void run_sgemm(const float* A, const float* B, float* C, int M, int N, int K,
                      const float* biasN, int relu,
                      float alpha = 1.f, float beta = 0.f, int ldc = -1, int ldb = -1)
{
    if (ldc < 0) ldc = N;
    if (ldb < 0) ldb = N;
    dim3 grid((N + 127) / 128, (M + 127) / 128);
    sgemm_k<<<grid, 256>>>(A, B, C, M, N, K, ldc, ldb, alpha, beta, biasN, relu);
}

extern "C" void kernel_launch(void* const* d_in, const int* in_sizes, int n_in,
                              void* d_out, int out_size)
{
    const float* x      = (const float*)d_in[0];
    const float* w_stem = (const float*)d_in[1];
    const float* b_stem = (const float*)d_in[2];
    const float* w1     = (const float*)d_in[3];
    const float* b1     = (const float*)d_in[4];
    const float* w2     = (const float*)d_in[5];
    const float* b2     = (const float*)d_in[6];
    const float* w3     = (const float*)d_in[7];
    const float* b3     = (const float*)d_in[8];
    const float* wd1    = (const float*)d_in[9];
    const float* bd1    = (const float*)d_in[10];
    const float* wd2    = (const float*)d_in[11];
    const float* bd2    = (const float*)d_in[12];
    const float* wf1    = (const float*)d_in[13];
    const float* bf1    = (const float*)d_in[14];
    const float* wf2    = (const float*)d_in[15];
    const float* bf2    = (const float*)d_in[16];
    const float* W_freq = (const float*)d_in[17];
    const float* b_freq = (const float*)d_in[18];
    const float* W_fu1  = (const float*)d_in[19];
    const float* b_fu1  = (const float*)d_in[20];
    const float* W_fu2  = (const float*)d_in[21];
    const float* b_fu2  = (const float*)d_in[22];
    const float* W_cls  = (const float*)d_in[23];
    const float* b_cls  = (const float*)d_in[24];
    const float* temp   = (const float*)d_in[25];
    float* out = (float*)d_out;

    float *h0, *h1, *h2, *h3, *hd1, *hd2, *hf1, *hf2;
    float *dctimg, *dctres, *wd1s, *Wre, *Wim, *D8;
    float *Zre, *Zim, *Ztre, *Ztim, *Gre, *Gim, *fftin;
    float *pooled, *comb, *buf1, *fused;
    cudaGetSymbolAddress((void**)&h0, g_h0);
    cudaGetSymbolAddress((void**)&h1, g_h1);
    cudaGetSymbolAddress((void**)&h2, g_h2);
    cudaGetSymbolAddress((void**)&h3, g_h3);
    cudaGetSymbolAddress((void**)&hd1, g_hd1);
    cudaGetSymbolAddress((void**)&hd2, g_hd2);
    cudaGetSymbolAddress((void**)&hf1, g_hf1);
    cudaGetSymbolAddress((void**)&hf2, g_hf2);
    cudaGetSymbolAddress((void**)&dctimg, g_dctimg);
    cudaGetSymbolAddress((void**)&dctres, g_dctres);
    cudaGetSymbolAddress((void**)&wd1s, g_wd1s);
    cudaGetSymbolAddress((void**)&Wre, g_Wre);
    cudaGetSymbolAddress((void**)&Wim, g_Wim);
    cudaGetSymbolAddress((void**)&D8, g_D8);
    cudaGetSymbolAddress((void**)&Zre, g_Zre);
    cudaGetSymbolAddress((void**)&Zim, g_Zim);
    cudaGetSymbolAddress((void**)&Ztre, g_Ztre);
    cudaGetSymbolAddress((void**)&Ztim, g_Ztim);
    cudaGetSymbolAddress((void**)&Gre, g_Gre);
    cudaGetSymbolAddress((void**)&Gim, g_Gim);
    cudaGetSymbolAddress((void**)&fftin, g_fftin);
    cudaGetSymbolAddress((void**)&pooled, g_pooled);
    cudaGetSymbolAddress((void**)&comb, g_comb);
    cudaGetSymbolAddress((void**)&buf1, g_buf1);
    cudaGetSymbolAddress((void**)&fused, g_fused);

    // ---- init constants ----
    genW_k<<<(HW + 255) / 256, 256>>>(Wre, Wim);
    genD8_k<<<1, 64>>>(D8);
    wsum_k<<<2, 256>>>(wd1, wd1s);

    // ---- CNN backbone ----
    dconv_k<7,7,117,64,1><<<dim3(98, 1, BATCH), 128>>>(
        x, w_stem, b_stem, h0, 3, 224, 224, 12544, 2, 2, (long long)HW, 3LL * HW);
    dconv_k<3,3,59,128,4><<<dim3(25, 1, BATCH), 256>>>(
        h0, w1, b1, h1, 64, 112, 112, 3136, 0, 0, 64LL * 12544, 12544LL);
    dconv_k<3,3,31,128,4><<<dim3(7, 2, BATCH), 256>>>(
        h1, w2, b2, h2, 128, 56, 56, 784, 0, 0, 64LL * 3136, 3136LL);
    dconv_k<3,3,17,128,4><<<dim3(2, 4, BATCH), 256>>>(
        h2, w3, b3, h3, 256, 28, 28, 196, 0, 0, 64LL * 784, 784LL);
    gap_k<<<(512 * BATCH + 255) / 256, 256>>>(h3, comb);

    // ---- DCT branch ----
    dct_mean_k<<<BATCH, 512>>>(x, D8, dctimg);
    resize_k<<<(BATCH * HW + 255) / 256, 256>>>(dctimg, dctres);
    dconv_k<3,3,115,32,1><<<dim3(98, 1, BATCH), 64>>>(
        dctres, wd1s, bd1, hd1, 1, 224, 224, 12544, 0, 0, 0LL, (long long)HW);
    dconv_k<3,3,59,64,4><<<dim3(25, 1, BATCH), 128>>>(
        hd1, wd2, bd2, hd2, 32, 112, 112, 3136, 0, 0, 64LL * 12544, 12544LL);
    pool7_k<<<(64 * BATCH * 49 + 255) / 256, 256>>>(hd2, pooled, 0);

    // ---- FFT branch (Hermitian-reduced DFT) ----
    run_sgemm(x, Wre, Zre, 43008, 128, 224, nullptr, 0, 1.f, 0.f, 128, 224);
    run_sgemm(x, Wim, Zim, 43008, 128, 224, nullptr, 0, 1.f, 0.f, 128, 224);
    {
        dim3 tgrid(7, 4, 192), tblk(32, 32);
        transpose_z_k<<<tgrid, tblk>>>(Zre, Ztre);
        transpose_z_k<<<tgrid, tblk>>>(Zim, Ztim);
    }
    dft2_k<<<dim3(2, 384), 256>>>(Ztre, Ztim, Wre, Wim, Gre, Gim);
    {
        dim3 tgrid(7, 7, 192), tblk(32, 32);
        fftin2_k<<<tgrid, tblk>>>(Gre, fftin, 0,  1.f);
        fftin2_k<<<tgrid, tblk>>>(Gim, fftin, 1, -1.f);
    }
    dconv_k<3,3,115,32,3><<<dim3(98, 1, BATCH), 64>>>(
        fftin, wf1, bf1, hf1, 6, 224, 224, 12544, 0, 0, (long long)BATCH * HW, (long long)HW);
    dconv_k<3,3,59,64,4><<<dim3(25, 1, BATCH), 128>>>(
        hf1, wf2, bf2, hf2, 32, 112, 112, 3136, 0, 0, 64LL * 12544, 12544LL);
    pool7_k<<<(64 * BATCH * 49 + 255) / 256, 256>>>(hf2, pooled, 3136);

    // ---- fusion + classifier ----
    run_sgemm(pooled, W_freq, comb + 512, 64, 512, 6272, b_freq, 1, 1.f, 0.f, 1024);
    run_sgemm(comb, W_fu1, buf1, 64, 1024, 1024, b_fu1, 1);
    run_sgemm(buf1, W_fu2, fused, 64, 512, 1024, b_fu2, 1);
    cls_k<<<1, 128>>>(fused, W_cls, b_cls, temp, out);
}